// round 4
// baseline (speedup 1.0000x reference)
#include <cuda_runtime.h>
#include <math.h>

// ---------------- problem constants ----------------
#define LL_ 4
#define B_  2
#define N_  4096
#define D_  1024
#define H_  16
#define HD_ 64
#define KP_ 256
#define FF_ 4096

#define BND_  (B_*N_*D_)          // 8388608
#define KPD_  (B_*KP_*D_)         // 524288
#define SCO_  (B_*H_*N_*KP_)      // 33554432
#define HBF_  (B_*N_*FF_)         // 33554432
#define SPLITK_ 8

// scratch layout (floats)
#define OFF_Q   ((size_t)0)
#define OFF_K   ((size_t)BND_)
#define OFF_V   ((size_t)2*BND_)
#define OFF_KP  ((size_t)3*BND_)
#define OFF_VP  (OFF_KP + KPD_)
#define OFF_SC  (OFF_VP + KPD_)
#define OFF_T1  (OFF_SC + SCO_)
#define OFF_Y   (OFF_T1 + BND_)
#define OFF_HB  (OFF_Y  + BND_)
#define OFF_XB  (OFF_HB + HBF_)
#define OFF_KPP (OFF_XB + BND_)
#define OFF_VPP (OFF_KPP + (size_t)SPLITK_*KPD_)
#define SCRATCH_FLOATS (OFF_VPP + (size_t)SPLITK_*KPD_)

__device__ float g_scratch[SCRATCH_FLOATS];

// ---------------- helpers ----------------
__device__ __forceinline__ float tf32r(float x) {
    unsigned u;
    asm("cvt.rna.tf32.f32 %0, %1;" : "=r"(u) : "f"(x));
    return __uint_as_float(u);
}

__device__ __forceinline__ float gelu_exact(float x) {
    return 0.5f * x * (1.0f + erff(x * 0.70710678118654752f));
}

__device__ __forceinline__ void mma_tf32(float c[4], const float4 a, const float2 b) {
    asm volatile(
        "mma.sync.aligned.m16n8k8.row.col.f32.tf32.tf32.f32 "
        "{%0,%1,%2,%3}, {%4,%5,%6,%7}, {%8,%9}, {%0,%1,%2,%3};"
        : "+f"(c[0]), "+f"(c[1]), "+f"(c[2]), "+f"(c[3])
        : "r"(__float_as_uint(a.x)), "r"(__float_as_uint(a.y)),
          "r"(__float_as_uint(a.z)), "r"(__float_as_uint(a.w)),
          "r"(__float_as_uint(b.x)), "r"(__float_as_uint(b.y)));
}

// ---------------- tf32 tensor-core GEMM, frag-packed smem + 2-stage pipe ----
// C(M,N) = A(M,K) * B(K,N)  [+ bias[col]] [gelu]
// TA: A stored K-major (K rows of M);  TB: B stored N-major (N rows of K)
// Shared layout packs each lane's mma fragment contiguously:
//   A: float4 at [kt][mtile][lane]  (components j=0..3 are a0..a3)
//   B: float2 at [kt][ntile][lane]  (components j=0..1 are b0..b1)
template<int BM, int BN, int BK, int WM, int WN, bool TA, bool TB, int EPI>
__global__ void __launch_bounds__((BM/WM)*(BN/WN)*32)
gemm_tc(const float* __restrict__ Ag, const float* __restrict__ Bg,
        float* __restrict__ Cg, const float* __restrict__ bias,
        int lda, int ldb, int ldc,
        long long sAi, long long sAo, long long sBi, long long sBo,
        long long sCi, long long sCo, long long sCk,
        int binner, int splitK, int Kd)
{
    constexpr int NWARP   = (BM/WM)*(BN/WN);
    constexpr int THREADS = NWARP*32;
    constexpr int MT16 = BM/16;
    constexpr int NT8  = BN/8;
    constexpr int KT8  = BK/8;
    constexpr int ITA = TA ? (BK*(BM/4))/THREADS : (BM*(BK/4))/THREADS;
    constexpr int ITB = TB ? (BN*(BK/4))/THREADS : (BK*(BN/4))/THREADS;

    __shared__ float As[2][BM*BK];
    __shared__ float Bs[2][BN*BK];

    const int z  = blockIdx.z;
    const int zk = z % splitK;
    const int zb = z / splitK;
    const int zi = zb % binner;
    const int zo = zb / binner;
    const float* A = Ag + zi*sAi + zo*sAo;
    const float* B = Bg + zi*sBi + zo*sBo;
    float*       C = Cg + zi*sCi + zo*sCo + (long long)zk*sCk;

    const int m0 = blockIdx.y * BM;
    const int n0 = blockIdx.x * BN;
    const int kPer = Kd / splitK;
    const int kbeg = zk * kPer;
    const int kend = kbeg + kPer;

    const int tid  = threadIdx.x;
    const int w    = tid >> 5;
    const int lane = tid & 31;
    constexpr int WGM = BM/WM;
    const int wmB  = (w % WGM) * WM;
    const int wnB  = (w / WGM) * WN;
    const int wm16 = wmB >> 4;
    const int wn8  = wnB >> 3;
    const int lr = lane >> 2;
    const int lc = lane & 3;

    constexpr int MT  = WM/16;
    constexpr int NTN = WN/8;
    float acc[MT][NTN][4];
#pragma unroll
    for (int i = 0; i < MT; i++)
#pragma unroll
        for (int j = 0; j < NTN; j++)
#pragma unroll
            for (int q = 0; q < 4; q++) acc[i][j][q] = 0.f;

    float4 rA[ITA], rB[ITB];

    // ---- gmem loads into regs ----
    auto ldgA = [&](int kb) {
#pragma unroll
        for (int t = 0; t < ITA; t++) {
            int i = tid + t*THREADS;
            if constexpr (!TA) {
                int m  = i / (BK/4);
                int k4 = (i - m*(BK/4)) * 4;
                rA[t] = *reinterpret_cast<const float4*>(A + (size_t)(m0+m)*lda + kb + k4);
            } else {
                int kq = i / (BM/4);
                int m4 = (i - kq*(BM/4)) * 4;
                rA[t] = *reinterpret_cast<const float4*>(A + (size_t)(kb+kq)*lda + m0 + m4);
            }
        }
    };
    auto ldgB = [&](int kb) {
#pragma unroll
        for (int t = 0; t < ITB; t++) {
            int i = tid + t*THREADS;
            if constexpr (!TB) {
                int kq = i / (BN/4);
                int n4 = (i - kq*(BN/4)) * 4;
                rB[t] = *reinterpret_cast<const float4*>(B + (size_t)(kb+kq)*ldb + n0 + n4);
            } else {
                int n  = i / (BK/4);
                int k4 = (i - n*(BK/4)) * 4;
                rB[t] = *reinterpret_cast<const float4*>(B + (size_t)(n0+n)*ldb + kb + k4);
            }
        }
    };

    // ---- scatter regs into frag-packed smem (tf32-rounded) ----
    auto stsA = [&](int s) {
#pragma unroll
        for (int t = 0; t < ITA; t++) {
            int i = tid + t*THREADS;
            float v[4] = {rA[t].x, rA[t].y, rA[t].z, rA[t].w};
            if constexpr (!TA) {
                int m  = i / (BK/4);
                int k4 = (i - m*(BK/4)) * 4;
                int mt = m >> 4, mr = m & 15, kt = k4 >> 3;
                int j  = (mr >> 3) | ((k4 & 4) >> 1);
                int base = (((kt*MT16 + mt)*32) + ((mr & 7) << 2))*4 + j;
#pragma unroll
                for (int c = 0; c < 4; c++) As[s][base + 4*c] = tf32r(v[c]);
            } else {
                int kq = i / (BM/4);
                int m4 = (i - kq*(BM/4)) * 4;
                int kt = kq >> 3, kc = kq & 7;
                int mt = m4 >> 4;
                int j  = ((m4 & 8) >> 3) | ((kc & 4) >> 1);
                int lane_b = ((m4 & 7) << 2) | (kc & 3);
                int base = (((kt*MT16 + mt)*32) + lane_b)*4 + j;
#pragma unroll
                for (int c = 0; c < 4; c++) As[s][base + 16*c] = tf32r(v[c]);
            }
        }
    };
    auto stsB = [&](int s) {
#pragma unroll
        for (int t = 0; t < ITB; t++) {
            int i = tid + t*THREADS;
            float v[4] = {rB[t].x, rB[t].y, rB[t].z, rB[t].w};
            if constexpr (!TB) {
                int kq = i / (BN/4);
                int n4 = (i - kq*(BN/4)) * 4;
                int kt = kq >> 3, kc = kq & 7;
                int nt = n4 >> 3;
                int j  = kc >> 2;
                int lane_b = ((n4 & 7) << 2) | (kc & 3);
                int base = (((kt*NT8 + nt)*32) + lane_b)*2 + j;
#pragma unroll
                for (int c = 0; c < 4; c++) Bs[s][base + 8*c] = tf32r(v[c]);
            } else {
                int n  = i / (BK/4);
                int k4 = (i - n*(BK/4)) * 4;
                int nt = n >> 3, nr = n & 7;
                int kt = k4 >> 3;
                int j  = (k4 & 4) >> 2;
                int base = (((kt*NT8 + nt)*32) + (nr << 2))*2 + j;
#pragma unroll
                for (int c = 0; c < 4; c++) Bs[s][base + 2*c] = tf32r(v[c]);
            }
        }
    };

    auto compute = [&](int s) {
        const float4* Ap = reinterpret_cast<const float4*>(As[s]);
        const float2* Bp = reinterpret_cast<const float2*>(Bs[s]);
#pragma unroll
        for (int kt = 0; kt < KT8; kt++) {
            float4 af[MT];
            float2 bf[NTN];
#pragma unroll
            for (int mt = 0; mt < MT; mt++)
                af[mt] = Ap[(kt*MT16 + wm16 + mt)*32 + lane];
#pragma unroll
            for (int nt = 0; nt < NTN; nt++)
                bf[nt] = Bp[(kt*NT8 + wn8 + nt)*32 + lane];
#pragma unroll
            for (int mt = 0; mt < MT; mt++)
#pragma unroll
                for (int nt = 0; nt < NTN; nt++)
                    mma_tf32(acc[mt][nt], af[mt], bf[nt]);
        }
    };

    // ---- pipelined mainloop ----
    ldgA(kbeg); ldgB(kbeg);
    stsA(0);    stsB(0);
    __syncthreads();
    int s = 0;
    for (int kb = kbeg; kb < kend; kb += BK) {
        bool more = (kb + BK) < kend;
        if (more) { ldgA(kb + BK); ldgB(kb + BK); }
        compute(s);
        if (more) { stsA(s ^ 1); stsB(s ^ 1); }
        __syncthreads();
        s ^= 1;
    }

    // ---- epilogue ----
#pragma unroll
    for (int mt = 0; mt < MT; mt++) {
#pragma unroll
        for (int nt = 0; nt < NTN; nt++) {
            int r = m0 + wmB + mt*16 + lr;
            int c = n0 + wnB + nt*8 + lc*2;
            float v0 = acc[mt][nt][0], v1 = acc[mt][nt][1];
            float v2 = acc[mt][nt][2], v3 = acc[mt][nt][3];
            if constexpr (EPI >= 1) {
                float bc0 = bias[c], bc1 = bias[c+1];
                v0 += bc0; v1 += bc1; v2 += bc0; v3 += bc1;
            }
            if constexpr (EPI == 2) {
                v0 = gelu_exact(v0); v1 = gelu_exact(v1);
                v2 = gelu_exact(v2); v3 = gelu_exact(v3);
            }
            *reinterpret_cast<float2*>(C + (size_t)r*ldc + c)     = make_float2(v0, v1);
            *reinterpret_cast<float2*>(C + (size_t)(r+8)*ldc + c) = make_float2(v2, v3);
        }
    }
}

// ---------------- split-K reduce (deterministic, no atomics) ----------------
__global__ void reduce_slices(const float* __restrict__ part, float* __restrict__ out,
                              int n, int slices, long long stride)
{
    int i = blockIdx.x * blockDim.x + threadIdx.x;
    if (i < n) {
        float s = 0.f;
        for (int t = 0; t < slices; t++) s += part[i + (long long)t*stride];
        out[i] = s;
    }
}

// ---------------- softmax over rows of 256 (scale 1/sqrt(64) folded in) -----
__global__ void softmax256(float* __restrict__ S, int nrows)
{
    int row = blockIdx.x * 8 + (threadIdx.x >> 5);
    if (row >= nrows) return;
    int lane = threadIdx.x & 31;
    float* p = S + (size_t)row * 256;
    float4 a = *reinterpret_cast<float4*>(p + lane*4);
    float4 b = *reinterpret_cast<float4*>(p + 128 + lane*4);
    const float sc = 0.125f;
    a.x *= sc; a.y *= sc; a.z *= sc; a.w *= sc;
    b.x *= sc; b.y *= sc; b.z *= sc; b.w *= sc;
    float m = fmaxf(fmaxf(fmaxf(a.x, a.y), fmaxf(a.z, a.w)),
                    fmaxf(fmaxf(b.x, b.y), fmaxf(b.z, b.w)));
#pragma unroll
    for (int o = 16; o; o >>= 1) m = fmaxf(m, __shfl_xor_sync(0xffffffffu, m, o));
    a.x = expf(a.x - m); a.y = expf(a.y - m); a.z = expf(a.z - m); a.w = expf(a.w - m);
    b.x = expf(b.x - m); b.y = expf(b.y - m); b.z = expf(b.z - m); b.w = expf(b.w - m);
    float s = a.x + a.y + a.z + a.w + b.x + b.y + b.z + b.w;
#pragma unroll
    for (int o = 16; o; o >>= 1) s += __shfl_xor_sync(0xffffffffu, s, o);
    float r = 1.0f / s;
    a.x *= r; a.y *= r; a.z *= r; a.w *= r;
    b.x *= r; b.y *= r; b.z *= r; b.w *= r;
    *reinterpret_cast<float4*>(p + lane*4)       = a;
    *reinterpret_cast<float4*>(p + 128 + lane*4) = b;
}

// ---------------- residual add + LayerNorm over D=1024 ----------------
__device__ __forceinline__ float block_sum_256(float v, float* sh)
{
#pragma unroll
    for (int o = 16; o; o >>= 1) v += __shfl_xor_sync(0xffffffffu, v, o);
    int w = threadIdx.x >> 5, lane = threadIdx.x & 31;
    if (lane == 0) sh[w] = v;
    __syncthreads();
    if (w == 0) {
        float t = (lane < 8) ? sh[lane] : 0.f;
#pragma unroll
        for (int o = 4; o; o >>= 1) t += __shfl_xor_sync(0xffffffffu, t, o);
        if (lane == 0) sh[0] = t;
    }
    __syncthreads();
    float r = sh[0];
    __syncthreads();
    return r;
}

__global__ void add_ln(const float* __restrict__ xa, const float* __restrict__ xb,
                       const float* __restrict__ g, const float* __restrict__ bt,
                       float* __restrict__ out)
{
    __shared__ float sh[8];
    int row = blockIdx.x;
    int tid = threadIdx.x;          // 256 threads, 4 elems each
    size_t base = (size_t)row * D_;
    float4 v = reinterpret_cast<const float4*>(xa + base)[tid];
    float4 r = reinterpret_cast<const float4*>(xb + base)[tid];
    v.x += r.x; v.y += r.y; v.z += r.z; v.w += r.w;
    float s = v.x + v.y + v.z + v.w;
    float mean = block_sum_256(s, sh) * (1.0f / D_);
    float d0 = v.x - mean, d1 = v.y - mean, d2 = v.z - mean, d3 = v.w - mean;
    float sq = d0*d0 + d1*d1 + d2*d2 + d3*d3;
    float var = block_sum_256(sq, sh) * (1.0f / D_);
    float rs = rsqrtf(var + 1e-12f);
    float4 gg = reinterpret_cast<const float4*>(g)[tid];
    float4 bb = reinterpret_cast<const float4*>(bt)[tid];
    float4 o;
    o.x = d0 * rs * gg.x + bb.x;
    o.y = d1 * rs * gg.y + bb.y;
    o.z = d2 * rs * gg.z + bb.z;
    o.w = d3 * rs * gg.w + bb.w;
    reinterpret_cast<float4*>(out + base)[tid] = o;
}

// ---------------- orchestration ----------------
extern "C" void kernel_launch(void* const* d_in, const int* in_sizes, int n_in,
                              void* d_out, int out_size)
{
    (void)in_sizes; (void)n_in; (void)out_size;
    const float* x   = (const float*)d_in[0];
    const float* Wq  = (const float*)d_in[1];
    const float* Wk  = (const float*)d_in[2];
    const float* Wv  = (const float*)d_in[3];
    const float* E   = (const float*)d_in[4];
    const float* F   = (const float*)d_in[5];
    const float* g1  = (const float*)d_in[6];
    const float* bl1 = (const float*)d_in[7];
    const float* W1  = (const float*)d_in[8];
    const float* bb1 = (const float*)d_in[9];
    const float* W2  = (const float*)d_in[10];
    const float* bb2 = (const float*)d_in[11];
    const float* g2  = (const float*)d_in[12];
    const float* bl2 = (const float*)d_in[13];
    float* out = (float*)d_out;

    float* S = nullptr;
    cudaGetSymbolAddress((void**)&S, g_scratch);
    float* qb  = S + OFF_Q;
    float* kb  = S + OFF_K;
    float* vb  = S + OFF_V;
    float* kp  = S + OFF_KP;
    float* vp  = S + OFF_VP;
    float* sc  = S + OFF_SC;
    float* t1  = S + OFF_T1;
    float* yb  = S + OFF_Y;
    float* hb  = S + OFF_HB;
    float* xb  = S + OFF_XB;
    float* kpp = S + OFF_KPP;
    float* vpp = S + OFF_VPP;

    const long long NDll  = (long long)N_ * D_;
    const long long KPDll = (long long)KP_ * D_;
    const long long NKPll = (long long)N_ * KP_;

    for (int l = 0; l < LL_; l++) {
        const float* xin = (l == 0) ? x : xb;

        // --- Q, K, V projections: [8192,1024] x [1024,1024], NN ---
        dim3 gQ(D_/128, (B_*N_)/128, 1);
        gemm_tc<128,128,16,64,64,false,false,0><<<gQ,128>>>(
            xin, Wq + (size_t)l*D_*D_, qb, nullptr,
            D_, D_, D_, 0,0,0,0,0,0,0, 1, 1, D_);
        gemm_tc<128,128,16,64,64,false,false,0><<<gQ,128>>>(
            xin, Wk + (size_t)l*D_*D_, kb, nullptr,
            D_, D_, D_, 0,0,0,0,0,0,0, 1, 1, D_);
        gemm_tc<128,128,16,64,64,false,false,0><<<gQ,128>>>(
            xin, Wv + (size_t)l*D_*D_, vb, nullptr,
            D_, D_, D_, 0,0,0,0,0,0,0, 1, 1, D_);

        // --- kp = E^T k, vp = F^T v : [256,1024], K=4096, TN, split-K=8 ---
        dim3 gP(D_/128, KP_/128, B_*SPLITK_);
        gemm_tc<128,128,16,64,64,true,false,0><<<gP,128>>>(
            E + (size_t)l*N_*KP_, kb, kpp, nullptr,
            KP_, D_, D_,
            0,0, 0,NDll, 0,KPDll, (long long)KPD_, 1, SPLITK_, N_);
        gemm_tc<128,128,16,64,64,true,false,0><<<gP,128>>>(
            F + (size_t)l*N_*KP_, vb, vpp, nullptr,
            KP_, D_, D_,
            0,0, 0,NDll, 0,KPDll, (long long)KPD_, 1, SPLITK_, N_);
        reduce_slices<<<KPD_/256,256>>>(kpp, kp, KPD_, SPLITK_, (long long)KPD_);
        reduce_slices<<<KPD_/256,256>>>(vpp, vp, KPD_, SPLITK_, (long long)KPD_);

        // --- scores[b,h] = Q_h Kp_h^T : [4096,256], K=64, NT, batched b*h ---
        dim3 gS(KP_/128, N_/128, B_*H_);
        gemm_tc<128,128,16,64,64,false,true,0><<<gS,128>>>(
            qb, kp, sc, nullptr,
            D_, D_, KP_,
            HD_, NDll, HD_, KPDll, NKPll, (long long)H_*NKPll, 0, H_, 1, HD_);

        // --- softmax (in place, scale 1/8 folded in) ---
        softmax256<<<(B_*H_*N_)/8,256>>>(sc, B_*H_*N_);

        // --- attn = P Vp_h : [4096,64], K=256, NN, batched ---
        dim3 gA(HD_/64, N_/128, B_*H_);
        gemm_tc<128,64,16,64,32,false,false,0><<<gA,128>>>(
            sc, vp, t1, nullptr,
            KP_, D_, D_,
            NKPll, (long long)H_*NKPll, HD_, KPDll, HD_, NDll, 0, H_, 1, KP_);

        // --- y = LN(attn + x) ---
        add_ln<<<B_*N_,256>>>(t1, xin, g1 + (size_t)l*D_, bl1 + (size_t)l*D_, yb);

        // --- h = gelu(y W1^T + b1) : [8192,4096], K=1024, NT ---
        dim3 gF1(FF_/128, (B_*N_)/128, 1);
        gemm_tc<128,128,16,64,64,false,true,2><<<gF1,128>>>(
            yb, W1 + (size_t)l*FF_*D_, hb, bb1 + (size_t)l*FF_,
            D_, D_, FF_, 0,0,0,0,0,0,0, 1, 1, D_);

        // --- o = h W2^T + b2 : [8192,1024], K=4096, NT ---
        dim3 gF2(D_/128, (B_*N_)/128, 1);
        gemm_tc<128,128,16,64,64,false,true,1><<<gF2,128>>>(
            hb, W2 + (size_t)l*D_*FF_, t1, bb2 + (size_t)l*D_,
            FF_, FF_, D_, 0,0,0,0,0,0,0, 1, 1, FF_);

        // --- x_next = LN(o + y) ---
        add_ln<<<B_*N_,256>>>(t1, yb, g2 + (size_t)l*D_, bl2 + (size_t)l*D_,
                              (l == LL_-1) ? out : xb);
    }
}

// round 5
// speedup vs baseline: 1.0329x; 1.0329x over previous
#include <cuda_runtime.h>
#include <math.h>

// ---------------- problem constants ----------------
#define LL_ 4
#define B_  2
#define N_  4096
#define D_  1024
#define H_  16
#define HD_ 64
#define KP_ 256
#define FF_ 4096

#define BND_  (B_*N_*D_)          // 8388608
#define KPD_  (B_*KP_*D_)         // 524288
#define SCO_  (B_*H_*N_*KP_)      // 33554432
#define HBF_  (B_*N_*FF_)         // 33554432
#define SPLITK_ 8

// scratch layout (floats)
#define OFF_Q   ((size_t)0)
#define OFF_K   ((size_t)BND_)
#define OFF_V   ((size_t)2*BND_)
#define OFF_KP  ((size_t)3*BND_)
#define OFF_VP  (OFF_KP + KPD_)
#define OFF_SC  (OFF_VP + KPD_)
#define OFF_T1  (OFF_SC + SCO_)
#define OFF_Y   (OFF_T1 + BND_)
#define OFF_HB  (OFF_Y  + BND_)
#define OFF_XB  (OFF_HB + HBF_)
#define OFF_KPP (OFF_XB + BND_)
#define OFF_VPP (OFF_KPP + (size_t)SPLITK_*KPD_)
#define SCRATCH_FLOATS (OFF_VPP + (size_t)SPLITK_*KPD_)

__device__ float g_scratch[SCRATCH_FLOATS];

// ---------------- helpers ----------------
__device__ __forceinline__ float tf32r(float x) {
    unsigned u;
    asm("cvt.rna.tf32.f32 %0, %1;" : "=r"(u) : "f"(x));
    return __uint_as_float(u);
}

__device__ __forceinline__ float gelu_exact(float x) {
    return 0.5f * x * (1.0f + erff(x * 0.70710678118654752f));
}

__device__ __forceinline__ void mma_tf32(float c[4], const float4 a, const float2 b) {
    asm volatile(
        "mma.sync.aligned.m16n8k8.row.col.f32.tf32.tf32.f32 "
        "{%0,%1,%2,%3}, {%4,%5,%6,%7}, {%8,%9}, {%0,%1,%2,%3};"
        : "+f"(c[0]), "+f"(c[1]), "+f"(c[2]), "+f"(c[3])
        : "r"(__float_as_uint(a.x)), "r"(__float_as_uint(a.y)),
          "r"(__float_as_uint(a.z)), "r"(__float_as_uint(a.w)),
          "r"(__float_as_uint(b.x)), "r"(__float_as_uint(b.y)));
}

// ---------------- tf32 tensor-core GEMM, frag-packed smem + 2-stage pipe ----
// C(M,N) = A(M,K) * B(K,N)  [+ bias[col]] [gelu]
// TA: A stored K-major (K rows of M);  TB: B stored N-major (N rows of K)
// Shared layout packs each lane's mma fragment contiguously:
//   A: float4 at [kt][mtile][lane]  (components j=0..3 are a0..a3)
//   B: float2 at [kt][ntile][lane]  (components j=0..1 are b0..b1)
template<int BM, int BN, int BK, int WM, int WN, bool TA, bool TB, int EPI>
__global__ void __launch_bounds__((BM/WM)*(BN/WN)*32, 2)
gemm_tc(const float* __restrict__ Ag, const float* __restrict__ Bg,
        float* __restrict__ Cg, const float* __restrict__ bias,
        int lda, int ldb, int ldc,
        long long sAi, long long sAo, long long sBi, long long sBo,
        long long sCi, long long sCo, long long sCk,
        int binner, int splitK, int Kd)
{
    constexpr int NWARP   = (BM/WM)*(BN/WN);
    constexpr int THREADS = NWARP*32;
    constexpr int MT16 = BM/16;
    constexpr int NT8  = BN/8;
    constexpr int KT8  = BK/8;
    constexpr int ITA = TA ? (BK*(BM/4))/THREADS : (BM*(BK/4))/THREADS;
    constexpr int ITB = TB ? (BN*(BK/4))/THREADS : (BK*(BN/4))/THREADS;

    __shared__ float As[2][BM*BK];
    __shared__ float Bs[2][BN*BK];

    const int z  = blockIdx.z;
    const int zk = z % splitK;
    const int zb = z / splitK;
    const int zi = zb % binner;
    const int zo = zb / binner;
    const float* A = Ag + zi*sAi + zo*sAo;
    const float* B = Bg + zi*sBi + zo*sBo;
    float*       C = Cg + zi*sCi + zo*sCo + (long long)zk*sCk;

    const int m0 = blockIdx.y * BM;
    const int n0 = blockIdx.x * BN;
    const int kPer = Kd / splitK;
    const int kbeg = zk * kPer;
    const int kend = kbeg + kPer;

    const int tid  = threadIdx.x;
    const int w    = tid >> 5;
    const int lane = tid & 31;
    constexpr int WGM = BM/WM;
    const int wmB  = (w % WGM) * WM;
    const int wnB  = (w / WGM) * WN;
    const int wm16 = wmB >> 4;
    const int wn8  = wnB >> 3;
    const int lr = lane >> 2;
    const int lc = lane & 3;

    constexpr int MT  = WM/16;
    constexpr int NTN = WN/8;
    float acc[MT][NTN][4];
#pragma unroll
    for (int i = 0; i < MT; i++)
#pragma unroll
        for (int j = 0; j < NTN; j++)
#pragma unroll
            for (int q = 0; q < 4; q++) acc[i][j][q] = 0.f;

    float4 rA[ITA], rB[ITB];

    // ---- gmem loads into regs ----
    auto ldgA = [&](int kb) {
#pragma unroll
        for (int t = 0; t < ITA; t++) {
            int i = tid + t*THREADS;
            if constexpr (!TA) {
                int m  = i / (BK/4);
                int k4 = (i - m*(BK/4)) * 4;
                rA[t] = *reinterpret_cast<const float4*>(A + (size_t)(m0+m)*lda + kb + k4);
            } else {
                int kq = i / (BM/4);
                int m4 = (i - kq*(BM/4)) * 4;
                rA[t] = *reinterpret_cast<const float4*>(A + (size_t)(kb+kq)*lda + m0 + m4);
            }
        }
    };
    auto ldgB = [&](int kb) {
#pragma unroll
        for (int t = 0; t < ITB; t++) {
            int i = tid + t*THREADS;
            if constexpr (!TB) {
                int kq = i / (BN/4);
                int n4 = (i - kq*(BN/4)) * 4;
                rB[t] = *reinterpret_cast<const float4*>(B + (size_t)(kb+kq)*ldb + n0 + n4);
            } else {
                int n  = i / (BK/4);
                int k4 = (i - n*(BK/4)) * 4;
                rB[t] = *reinterpret_cast<const float4*>(B + (size_t)(n0+n)*ldb + kb + k4);
            }
        }
    };

    // ---- scatter regs into frag-packed smem (tf32-rounded) ----
    auto stsA = [&](int s) {
#pragma unroll
        for (int t = 0; t < ITA; t++) {
            int i = tid + t*THREADS;
            float v[4] = {rA[t].x, rA[t].y, rA[t].z, rA[t].w};
            if constexpr (!TA) {
                int m  = i / (BK/4);
                int k4 = (i - m*(BK/4)) * 4;
                int mt = m >> 4, mr = m & 15, kt = k4 >> 3;
                int j  = (mr >> 3) | ((k4 & 4) >> 1);
                int base = (((kt*MT16 + mt)*32) + ((mr & 7) << 2))*4 + j;
#pragma unroll
                for (int c = 0; c < 4; c++) As[s][base + 4*c] = tf32r(v[c]);
            } else {
                int kq = i / (BM/4);
                int m4 = (i - kq*(BM/4)) * 4;
                int kt = kq >> 3, kc = kq & 7;
                int mt = m4 >> 4;
                int j  = ((m4 & 8) >> 3) | ((kc & 4) >> 1);
                int lane_b = ((m4 & 7) << 2) | (kc & 3);
                int base = (((kt*MT16 + mt)*32) + lane_b)*4 + j;
#pragma unroll
                for (int c = 0; c < 4; c++) As[s][base + 16*c] = tf32r(v[c]);
            }
        }
    };
    auto stsB = [&](int s) {
#pragma unroll
        for (int t = 0; t < ITB; t++) {
            int i = tid + t*THREADS;
            float v[4] = {rB[t].x, rB[t].y, rB[t].z, rB[t].w};
            if constexpr (!TB) {
                int kq = i / (BN/4);
                int n4 = (i - kq*(BN/4)) * 4;
                int kt = kq >> 3, kc = kq & 7;
                int nt = n4 >> 3;
                int j  = kc >> 2;
                int lane_b = ((n4 & 7) << 2) | (kc & 3);
                int base = (((kt*NT8 + nt)*32) + lane_b)*2 + j;
#pragma unroll
                for (int c = 0; c < 4; c++) Bs[s][base + 8*c] = tf32r(v[c]);
            } else {
                int n  = i / (BK/4);
                int k4 = (i - n*(BK/4)) * 4;
                int nt = n >> 3, nr = n & 7;
                int kt = k4 >> 3;
                int j  = (k4 & 4) >> 2;
                int base = (((kt*NT8 + nt)*32) + (nr << 2))*2 + j;
#pragma unroll
                for (int c = 0; c < 4; c++) Bs[s][base + 2*c] = tf32r(v[c]);
            }
        }
    };

    auto compute = [&](int s) {
        const float4* Ap = reinterpret_cast<const float4*>(As[s]);
        const float2* Bp = reinterpret_cast<const float2*>(Bs[s]);
#pragma unroll
        for (int kt = 0; kt < KT8; kt++) {
            float4 af[MT];
            float2 bf[NTN];
#pragma unroll
            for (int mt = 0; mt < MT; mt++)
                af[mt] = Ap[(kt*MT16 + wm16 + mt)*32 + lane];
#pragma unroll
            for (int nt = 0; nt < NTN; nt++)
                bf[nt] = Bp[(kt*NT8 + wn8 + nt)*32 + lane];
#pragma unroll
            for (int mt = 0; mt < MT; mt++)
#pragma unroll
                for (int nt = 0; nt < NTN; nt++)
                    mma_tf32(acc[mt][nt], af[mt], bf[nt]);
        }
    };

    // ---- pipelined mainloop ----
    ldgA(kbeg); ldgB(kbeg);
    stsA(0);    stsB(0);
    __syncthreads();
    int s = 0;
    for (int kb = kbeg; kb < kend; kb += BK) {
        bool more = (kb + BK) < kend;
        if (more) { ldgA(kb + BK); ldgB(kb + BK); }
        compute(s);
        if (more) { stsA(s ^ 1); stsB(s ^ 1); }
        __syncthreads();
        s ^= 1;
    }

    // ---- epilogue ----
#pragma unroll
    for (int mt = 0; mt < MT; mt++) {
#pragma unroll
        for (int nt = 0; nt < NTN; nt++) {
            int r = m0 + wmB + mt*16 + lr;
            int c = n0 + wnB + nt*8 + lc*2;
            float v0 = acc[mt][nt][0], v1 = acc[mt][nt][1];
            float v2 = acc[mt][nt][2], v3 = acc[mt][nt][3];
            if constexpr (EPI >= 1) {
                float bc0 = bias[c], bc1 = bias[c+1];
                v0 += bc0; v1 += bc1; v2 += bc0; v3 += bc1;
            }
            if constexpr (EPI == 2) {
                v0 = gelu_exact(v0); v1 = gelu_exact(v1);
                v2 = gelu_exact(v2); v3 = gelu_exact(v3);
            }
            *reinterpret_cast<float2*>(C + (size_t)r*ldc + c)     = make_float2(v0, v1);
            *reinterpret_cast<float2*>(C + (size_t)(r+8)*ldc + c) = make_float2(v2, v3);
        }
    }
}

// ---------------- split-K reduce (deterministic, no atomics) ----------------
__global__ void reduce_slices(const float* __restrict__ part, float* __restrict__ out,
                              int n, int slices, long long stride)
{
    int i = blockIdx.x * blockDim.x + threadIdx.x;
    if (i < n) {
        float s = 0.f;
        for (int t = 0; t < slices; t++) s += part[i + (long long)t*stride];
        out[i] = s;
    }
}

// ---------------- softmax over rows of 256 (scale 1/sqrt(64) folded in) -----
__global__ void softmax256(float* __restrict__ S, int nrows)
{
    int row = blockIdx.x * 8 + (threadIdx.x >> 5);
    if (row >= nrows) return;
    int lane = threadIdx.x & 31;
    float* p = S + (size_t)row * 256;
    float4 a = *reinterpret_cast<float4*>(p + lane*4);
    float4 b = *reinterpret_cast<float4*>(p + 128 + lane*4);
    const float sc = 0.125f;
    a.x *= sc; a.y *= sc; a.z *= sc; a.w *= sc;
    b.x *= sc; b.y *= sc; b.z *= sc; b.w *= sc;
    float m = fmaxf(fmaxf(fmaxf(a.x, a.y), fmaxf(a.z, a.w)),
                    fmaxf(fmaxf(b.x, b.y), fmaxf(b.z, b.w)));
#pragma unroll
    for (int o = 16; o; o >>= 1) m = fmaxf(m, __shfl_xor_sync(0xffffffffu, m, o));
    a.x = expf(a.x - m); a.y = expf(a.y - m); a.z = expf(a.z - m); a.w = expf(a.w - m);
    b.x = expf(b.x - m); b.y = expf(b.y - m); b.z = expf(b.z - m); b.w = expf(b.w - m);
    float s = a.x + a.y + a.z + a.w + b.x + b.y + b.z + b.w;
#pragma unroll
    for (int o = 16; o; o >>= 1) s += __shfl_xor_sync(0xffffffffu, s, o);
    float r = 1.0f / s;
    a.x *= r; a.y *= r; a.z *= r; a.w *= r;
    b.x *= r; b.y *= r; b.z *= r; b.w *= r;
    *reinterpret_cast<float4*>(p + lane*4)       = a;
    *reinterpret_cast<float4*>(p + 128 + lane*4) = b;
}

// ---------------- residual add + LayerNorm over D=1024 ----------------
__device__ __forceinline__ float block_sum_256(float v, float* sh)
{
#pragma unroll
    for (int o = 16; o; o >>= 1) v += __shfl_xor_sync(0xffffffffu, v, o);
    int w = threadIdx.x >> 5, lane = threadIdx.x & 31;
    if (lane == 0) sh[w] = v;
    __syncthreads();
    if (w == 0) {
        float t = (lane < 8) ? sh[lane] : 0.f;
#pragma unroll
        for (int o = 4; o; o >>= 1) t += __shfl_xor_sync(0xffffffffu, t, o);
        if (lane == 0) sh[0] = t;
    }
    __syncthreads();
    float r = sh[0];
    __syncthreads();
    return r;
}

__global__ void add_ln(const float* __restrict__ xa, const float* __restrict__ xb,
                       const float* __restrict__ g, const float* __restrict__ bt,
                       float* __restrict__ out)
{
    __shared__ float sh[8];
    int row = blockIdx.x;
    int tid = threadIdx.x;          // 256 threads, 4 elems each
    size_t base = (size_t)row * D_;
    float4 v = reinterpret_cast<const float4*>(xa + base)[tid];
    float4 r = reinterpret_cast<const float4*>(xb + base)[tid];
    v.x += r.x; v.y += r.y; v.z += r.z; v.w += r.w;
    float s = v.x + v.y + v.z + v.w;
    float mean = block_sum_256(s, sh) * (1.0f / D_);
    float d0 = v.x - mean, d1 = v.y - mean, d2 = v.z - mean, d3 = v.w - mean;
    float sq = d0*d0 + d1*d1 + d2*d2 + d3*d3;
    float var = block_sum_256(sq, sh) * (1.0f / D_);
    float rs = rsqrtf(var + 1e-12f);
    float4 gg = reinterpret_cast<const float4*>(g)[tid];
    float4 bb = reinterpret_cast<const float4*>(bt)[tid];
    float4 o;
    o.x = d0 * rs * gg.x + bb.x;
    o.y = d1 * rs * gg.y + bb.y;
    o.z = d2 * rs * gg.z + bb.z;
    o.w = d3 * rs * gg.w + bb.w;
    reinterpret_cast<float4*>(out + base)[tid] = o;
}

// ---------------- orchestration ----------------
extern "C" void kernel_launch(void* const* d_in, const int* in_sizes, int n_in,
                              void* d_out, int out_size)
{
    (void)in_sizes; (void)n_in; (void)out_size;
    const float* x   = (const float*)d_in[0];
    const float* Wq  = (const float*)d_in[1];
    const float* Wk  = (const float*)d_in[2];
    const float* Wv  = (const float*)d_in[3];
    const float* E   = (const float*)d_in[4];
    const float* F   = (const float*)d_in[5];
    const float* g1  = (const float*)d_in[6];
    const float* bl1 = (const float*)d_in[7];
    const float* W1  = (const float*)d_in[8];
    const float* bb1 = (const float*)d_in[9];
    const float* W2  = (const float*)d_in[10];
    const float* bb2 = (const float*)d_in[11];
    const float* g2  = (const float*)d_in[12];
    const float* bl2 = (const float*)d_in[13];
    float* out = (float*)d_out;

    float* S = nullptr;
    cudaGetSymbolAddress((void**)&S, g_scratch);
    float* qb  = S + OFF_Q;
    float* kb  = S + OFF_K;
    float* vb  = S + OFF_V;
    float* kp  = S + OFF_KP;
    float* vp  = S + OFF_VP;
    float* sc  = S + OFF_SC;
    float* t1  = S + OFF_T1;
    float* yb  = S + OFF_Y;
    float* hb  = S + OFF_HB;
    float* xb  = S + OFF_XB;
    float* kpp = S + OFF_KPP;
    float* vpp = S + OFF_VPP;

    const long long NDll  = (long long)N_ * D_;
    const long long KPDll = (long long)KP_ * D_;
    const long long NKPll = (long long)N_ * KP_;

    for (int l = 0; l < LL_; l++) {
        const float* xin = (l == 0) ? x : xb;

        // --- Q, K, V projections: [8192,1024] x [1024,1024], NN ---
        dim3 gQ(D_/128, (B_*N_)/128, 1);
        gemm_tc<128,128,16,32,64,false,false,0><<<gQ,256>>>(
            xin, Wq + (size_t)l*D_*D_, qb, nullptr,
            D_, D_, D_, 0,0,0,0,0,0,0, 1, 1, D_);
        gemm_tc<128,128,16,32,64,false,false,0><<<gQ,256>>>(
            xin, Wk + (size_t)l*D_*D_, kb, nullptr,
            D_, D_, D_, 0,0,0,0,0,0,0, 1, 1, D_);
        gemm_tc<128,128,16,32,64,false,false,0><<<gQ,256>>>(
            xin, Wv + (size_t)l*D_*D_, vb, nullptr,
            D_, D_, D_, 0,0,0,0,0,0,0, 1, 1, D_);

        // --- kp = E^T k, vp = F^T v : [256,1024], K=4096, TN, split-K=8 ---
        dim3 gP(D_/128, KP_/128, B_*SPLITK_);
        gemm_tc<128,128,16,32,64,true,false,0><<<gP,256>>>(
            E + (size_t)l*N_*KP_, kb, kpp, nullptr,
            KP_, D_, D_,
            0,0, 0,NDll, 0,KPDll, (long long)KPD_, 1, SPLITK_, N_);
        gemm_tc<128,128,16,32,64,true,false,0><<<gP,256>>>(
            F + (size_t)l*N_*KP_, vb, vpp, nullptr,
            KP_, D_, D_,
            0,0, 0,NDll, 0,KPDll, (long long)KPD_, 1, SPLITK_, N_);
        reduce_slices<<<KPD_/256,256>>>(kpp, kp, KPD_, SPLITK_, (long long)KPD_);
        reduce_slices<<<KPD_/256,256>>>(vpp, vp, KPD_, SPLITK_, (long long)KPD_);

        // --- scores[b,h] = Q_h Kp_h^T : [4096,256], K=64, NT, batched b*h ---
        dim3 gS(KP_/128, N_/128, B_*H_);
        gemm_tc<128,128,16,32,64,false,true,0><<<gS,256>>>(
            qb, kp, sc, nullptr,
            D_, D_, KP_,
            HD_, NDll, HD_, KPDll, NKPll, (long long)H_*NKPll, 0, H_, 1, HD_);

        // --- softmax (in place, scale 1/8 folded in) ---
        softmax256<<<(B_*H_*N_)/8,256>>>(sc, B_*H_*N_);

        // --- attn = P Vp_h : [4096,64], K=256, NN, batched ---
        dim3 gA(HD_/64, N_/128, B_*H_);
        gemm_tc<128,64,16,32,32,false,false,0><<<gA,256>>>(
            sc, vp, t1, nullptr,
            KP_, D_, D_,
            NKPll, (long long)H_*NKPll, HD_, KPDll, HD_, NDll, 0, H_, 1, KP_);

        // --- y = LN(attn + x) ---
        add_ln<<<B_*N_,256>>>(t1, xin, g1 + (size_t)l*D_, bl1 + (size_t)l*D_, yb);

        // --- h = gelu(y W1^T + b1) : [8192,4096], K=1024, NT ---
        dim3 gF1(FF_/128, (B_*N_)/128, 1);
        gemm_tc<128,128,16,32,64,false,true,2><<<gF1,256>>>(
            yb, W1 + (size_t)l*FF_*D_, hb, bb1 + (size_t)l*FF_,
            D_, D_, FF_, 0,0,0,0,0,0,0, 1, 1, D_);

        // --- o = h W2^T + b2 : [8192,1024], K=4096, NT ---
        dim3 gF2(D_/128, (B_*N_)/128, 1);
        gemm_tc<128,128,16,32,64,false,true,1><<<gF2,256>>>(
            hb, W2 + (size_t)l*D_*FF_, t1, bb2 + (size_t)l*D_,
            FF_, FF_, D_, 0,0,0,0,0,0,0, 1, 1, FF_);

        // --- x_next = LN(o + y) ---
        add_ln<<<B_*N_,256>>>(t1, yb, g2 + (size_t)l*D_, bl2 + (size_t)l*D_,
                              (l == LL_-1) ? out : xb);
    }
}

// round 7
// speedup vs baseline: 2.7194x; 2.6328x over previous
#include <cuda_runtime.h>
#include <math.h>
#include <stdint.h>

// ---------------- problem constants ----------------
#define LL_ 4
#define B_  2
#define N_  4096
#define D_  1024
#define H_  16
#define HD_ 64
#define KP_ 256
#define FF_ 4096

#define BND_  (B_*N_*D_)
#define KPD_  (B_*KP_*D_)
#define SCO_  (B_*H_*N_*KP_)
#define HBF_  (B_*N_*FF_)
#define SPLITK_ 8

// scratch layout (floats)
#define OFF_Q   ((size_t)0)
#define OFF_K   ((size_t)BND_)
#define OFF_V   ((size_t)2*BND_)
#define OFF_KP  ((size_t)3*BND_)
#define OFF_VP  (OFF_KP + KPD_)
#define OFF_SC  (OFF_VP + KPD_)
#define OFF_T1  (OFF_SC + SCO_)
#define OFF_Y   (OFF_T1 + BND_)
#define OFF_HB  (OFF_Y  + BND_)
#define OFF_XB  (OFF_HB + HBF_)
#define OFF_KPP (OFF_XB + BND_)
#define OFF_VPP (OFF_KPP + (size_t)SPLITK_*KPD_)
#define OFF_WT  (OFF_VPP + (size_t)SPLITK_*KPD_)            // 3*L*D*D (WqT,WkT,WvT)
#define OFF_ET  (OFF_WT  + (size_t)3*LL_*D_*D_)
#define OFF_FT  (OFF_ET  + (size_t)LL_*KP_*N_)
#define OFF_KBT (OFF_FT  + (size_t)LL_*KP_*N_)
#define OFF_VBT (OFF_KBT + (size_t)BND_)
#define OFF_VPT (OFF_VBT + (size_t)BND_)
#define OFF_W1R (OFF_VPT + (size_t)KPD_)
#define OFF_W2R (OFF_W1R + (size_t)LL_*FF_*D_)
#define SCRATCH_FLOATS (OFF_W2R + (size_t)LL_*D_*FF_)

__device__ float g_scratch[SCRATCH_FLOATS];

// ---------------- helpers ----------------
__device__ __forceinline__ float tf32r(float x) {
    unsigned u;
    asm("cvt.rna.tf32.f32 %0, %1;" : "=r"(u) : "f"(x));
    return __uint_as_float(u);
}
__device__ __forceinline__ void tf32r_u(uint32_t& x) {
    asm("cvt.rna.tf32.f32 %0, %1;" : "=r"(x) : "f"(__uint_as_float(x)));
}
__device__ __forceinline__ float gelu_exact(float x) {
    return 0.5f * x * (1.0f + erff(x * 0.70710678118654752f));
}
__device__ __forceinline__ uint32_t smem_u32(const void* p) {
    uint32_t a;
    asm("{ .reg .u64 t; cvta.to.shared.u64 t, %1; cvt.u32.u64 %0, t; }" : "=r"(a) : "l"(p));
    return a;
}
__device__ __forceinline__ void ldsm4(uint32_t r[4], uint32_t a) {
    asm volatile("ldmatrix.sync.aligned.m8n8.x4.shared.b16 {%0,%1,%2,%3}, [%4];"
                 : "=r"(r[0]), "=r"(r[1]), "=r"(r[2]), "=r"(r[3]) : "r"(a));
}
__device__ __forceinline__ void mma8(float c[4], const uint32_t a[4], uint32_t b0, uint32_t b1) {
    asm volatile(
        "mma.sync.aligned.m16n8k8.row.col.f32.tf32.tf32.f32 "
        "{%0,%1,%2,%3}, {%4,%5,%6,%7}, {%8,%9}, {%0,%1,%2,%3};"
        : "+f"(c[0]), "+f"(c[1]), "+f"(c[2]), "+f"(c[3])
        : "r"(a[0]), "r"(a[1]), "r"(a[2]), "r"(a[3]), "r"(b0), "r"(b1));
}
#define CP16(dst, src) asm volatile("cp.async.cg.shared.global [%0], [%1], 16;" :: "r"(dst), "l"(src))
#define CP_COMMIT()    asm volatile("cp.async.commit_group;" ::: "memory")
#define CP_WAIT(N)     asm volatile("cp.async.wait_group %0;" :: "n"(N) : "memory")

// ---------------- tf32 mma.sync GEMM: swizzled smem + ldmatrix + cp.async ----
// C(M,N) = A(M,K)*B^T(N,K): A gmem [m][k] (lda), B gmem [n][k] (ldb). BM=128, BK=32.
// smem tiles row-major [row][32 floats], 128B rows, 16B-unit xor swizzle u^(row&7).
// CA/CB: apply tf32 rounding to A/B fragments (operand not pre-rounded).
// RO: tf32-round outputs. EPI: 0 none, 1 +bias, 2 +bias+gelu.
template<int BN, int EPI, bool CA, bool CB, bool RO>
__global__ void __launch_bounds__(BN == 128 ? 256 : 128, BN == 128 ? 2 : 4)
gemm_ls(const float* __restrict__ Ag, const float* __restrict__ Bg,
        float* __restrict__ Cg, const float* __restrict__ bias,
        int lda, int ldb, int ldc,
        long long sAi, long long sAo, long long sBi, long long sBo,
        long long sCi, long long sCo, long long sCk,
        int binner, int splitK, int Kd)
{
    constexpr int BM = 128, BK = 32;
    constexpr int THREADS = (BN == 128) ? 256 : 128;
    constexpr int ABY = BM * BK * 4;             // 16KB
    constexpr int BBY = BN * BK * 4;
    constexpr int STG = ABY + BBY;

    extern __shared__ char sm[];
    const uint32_t smb = smem_u32(sm);
    const int tid = threadIdx.x, w = tid >> 5, lane = tid & 31;
    const int l7 = lane & 7, sel = lane >> 3;

    const int z  = blockIdx.z;
    const int zk = z % splitK;
    const int zb = z / splitK;
    const int zi = zb % binner;
    const int zo = zb / binner;
    const float* A = Ag + zi * sAi + zo * sAo;
    const float* Bp = Bg + zi * sBi + zo * sBo;
    float*       C = Cg + zi * sCi + zo * sCo + (long long)zk * sCk;

    const int m0 = blockIdx.y * BM;
    const int n0 = blockIdx.x * BN;
    const int kPer = Kd / splitK;
    const int kbeg = zk * kPer;
    const int ntiles = kPer / BK;

    const int wmB = (w & 3) * 32;          // 4 m-groups of 32
    const int wnB = (w >> 2) * 64;         // n-groups of 64 (0 for BN=64)
    const int lr = lane >> 2, lc = lane & 3;

    float acc[2][8][4];
#pragma unroll
    for (int i = 0; i < 2; i++)
#pragma unroll
        for (int j = 0; j < 8; j++)
#pragma unroll
            for (int q = 0; q < 4; q++) acc[i][j][q] = 0.f;

    auto stage = [&](int s, int kb) {
        uint32_t sa = smb + (uint32_t)(s * STG);
        uint32_t sb2 = sa + ABY;
#pragma unroll
        for (int t = 0; t < (BM * BK / 4) / THREADS; t++) {
            int i = tid + t * THREADS;
            int m = i >> 3, kq = i & 7;
            uint32_t dst = sa + (uint32_t)(m * 128 + ((kq ^ (m & 7)) << 4));
            const void* src = (const void*)(A + (size_t)(m0 + m) * lda + kb + kq * 4);
            CP16(dst, src);
        }
#pragma unroll
        for (int t = 0; t < (BN * BK / 4) / THREADS; t++) {
            int i = tid + t * THREADS;
            int n = i >> 3, kq = i & 7;
            uint32_t dst = sb2 + (uint32_t)(n * 128 + ((kq ^ (n & 7)) << 4));
            const void* src = (const void*)(Bp + (size_t)(n0 + n) * ldb + kb + kq * 4);
            CP16(dst, src);
        }
        CP_COMMIT();
    };

    auto compute = [&](int s) {
        uint32_t sa = smb + (uint32_t)(s * STG);
        uint32_t sb2 = sa + ABY;
        uint32_t arow0 = sa + (uint32_t)((wmB + ((sel & 1) << 3) + l7) * 128);
        uint32_t arow1 = arow0 + 16 * 128;
        uint32_t brow[4];
#pragma unroll
        for (int p = 0; p < 4; p++)
            brow[p] = sb2 + (uint32_t)((wnB + p * 16 + ((sel >> 1) << 3) + l7) * 128);
        const int aub = sel >> 1, bub = sel & 1;
#pragma unroll
        for (int kt = 0; kt < 4; kt++) {
            uint32_t a[2][4], b[4][4];
            uint32_t au = (uint32_t)(((2 * kt + aub) ^ l7) << 4);
            uint32_t bu = (uint32_t)(((2 * kt + bub) ^ l7) << 4);
            ldsm4(a[0], arow0 + au);
            ldsm4(a[1], arow1 + au);
#pragma unroll
            for (int p = 0; p < 4; p++) ldsm4(b[p], brow[p] + bu);
            if constexpr (CA) {
#pragma unroll
                for (int mt = 0; mt < 2; mt++)
#pragma unroll
                    for (int j = 0; j < 4; j++) tf32r_u(a[mt][j]);
            }
            if constexpr (CB) {
#pragma unroll
                for (int p = 0; p < 4; p++)
#pragma unroll
                    for (int j = 0; j < 4; j++) tf32r_u(b[p][j]);
            }
#pragma unroll
            for (int mt = 0; mt < 2; mt++)
#pragma unroll
                for (int p = 0; p < 4; p++) {
                    mma8(acc[mt][2 * p],     a[mt], b[p][0], b[p][1]);
                    mma8(acc[mt][2 * p + 1], a[mt], b[p][2], b[p][3]);
                }
        }
    };

    stage(0, kbeg);
    for (int t = 0; t < ntiles; t++) {
        int s = t & 1;
        if (t + 1 < ntiles) {
            stage(s ^ 1, kbeg + (t + 1) * BK);
            CP_WAIT(1);
        } else {
            CP_WAIT(0);
        }
        __syncthreads();
        compute(s);
        __syncthreads();
    }

    // ---- epilogue ----
#pragma unroll
    for (int mt = 0; mt < 2; mt++) {
#pragma unroll
        for (int nt = 0; nt < 8; nt++) {
            int r = m0 + wmB + mt * 16 + lr;
            int c = n0 + wnB + nt * 8 + lc * 2;
            float v0 = acc[mt][nt][0], v1 = acc[mt][nt][1];
            float v2 = acc[mt][nt][2], v3 = acc[mt][nt][3];
            if constexpr (EPI >= 1) {
                float bc0 = bias[c], bc1 = bias[c + 1];
                v0 += bc0; v1 += bc1; v2 += bc0; v3 += bc1;
            }
            if constexpr (EPI == 2) {
                v0 = gelu_exact(v0); v1 = gelu_exact(v1);
                v2 = gelu_exact(v2); v3 = gelu_exact(v3);
            }
            if constexpr (RO) {
                v0 = tf32r(v0); v1 = tf32r(v1); v2 = tf32r(v2); v3 = tf32r(v3);
            }
            *reinterpret_cast<float2*>(C + (size_t)r * ldc + c)       = make_float2(v0, v1);
            *reinterpret_cast<float2*>(C + (size_t)(r + 8) * ldc + c) = make_float2(v2, v3);
        }
    }
}

// ---------------- batched 32x32 tiled transpose (tf32-rounds output) --------
__global__ void transpose_r(const float* __restrict__ in, float* __restrict__ out,
                            int R, int C)
{
    __shared__ float t[32][33];
    long long zoff = (long long)blockIdx.z * R * C;
    int c0 = blockIdx.x * 32, r0 = blockIdx.y * 32;
    int x = threadIdx.x, y = threadIdx.y;
#pragma unroll
    for (int i = 0; i < 32; i += 8)
        t[y + i][x] = in[zoff + (long long)(r0 + y + i) * C + (c0 + x)];
    __syncthreads();
#pragma unroll
    for (int i = 0; i < 32; i += 8)
        out[zoff + (long long)(c0 + y + i) * R + (r0 + x)] = tf32r(t[x][y + i]);
}

// ---------------- elementwise tf32-round copy ----------------
__global__ void round_copy4(const float4* __restrict__ in, float4* __restrict__ out, int n4)
{
    int i = blockIdx.x * blockDim.x + threadIdx.x;
    if (i < n4) {
        float4 v = in[i];
        v.x = tf32r(v.x); v.y = tf32r(v.y); v.z = tf32r(v.z); v.w = tf32r(v.w);
        out[i] = v;
    }
}

// ---------------- split-K reduce (deterministic; rounds output) -------------
__global__ void reduce_slices(const float* __restrict__ part, float* __restrict__ out,
                              int n, int slices, long long stride)
{
    int i = blockIdx.x * blockDim.x + threadIdx.x;
    if (i < n) {
        float s = 0.f;
        for (int t = 0; t < slices; t++) s += part[i + (long long)t * stride];
        out[i] = tf32r(s);
    }
}

// ---------------- softmax over rows of 256 (scale 1/8; rounds output) -------
__global__ void softmax256(float* __restrict__ S, int nrows)
{
    int row = blockIdx.x * 8 + (threadIdx.x >> 5);
    if (row >= nrows) return;
    int lane = threadIdx.x & 31;
    float* p = S + (size_t)row * 256;
    float4 a = *reinterpret_cast<float4*>(p + lane * 4);
    float4 b = *reinterpret_cast<float4*>(p + 128 + lane * 4);
    const float sc = 0.125f;
    a.x *= sc; a.y *= sc; a.z *= sc; a.w *= sc;
    b.x *= sc; b.y *= sc; b.z *= sc; b.w *= sc;
    float m = fmaxf(fmaxf(fmaxf(a.x, a.y), fmaxf(a.z, a.w)),
                    fmaxf(fmaxf(b.x, b.y), fmaxf(b.z, b.w)));
#pragma unroll
    for (int o = 16; o; o >>= 1) m = fmaxf(m, __shfl_xor_sync(0xffffffffu, m, o));
    a.x = expf(a.x - m); a.y = expf(a.y - m); a.z = expf(a.z - m); a.w = expf(a.w - m);
    b.x = expf(b.x - m); b.y = expf(b.y - m); b.z = expf(b.z - m); b.w = expf(b.w - m);
    float s = a.x + a.y + a.z + a.w + b.x + b.y + b.z + b.w;
#pragma unroll
    for (int o = 16; o; o >>= 1) s += __shfl_xor_sync(0xffffffffu, s, o);
    float r = 1.0f / s;
    a.x = tf32r(a.x * r); a.y = tf32r(a.y * r); a.z = tf32r(a.z * r); a.w = tf32r(a.w * r);
    b.x = tf32r(b.x * r); b.y = tf32r(b.y * r); b.z = tf32r(b.z * r); b.w = tf32r(b.w * r);
    *reinterpret_cast<float4*>(p + lane * 4)       = a;
    *reinterpret_cast<float4*>(p + 128 + lane * 4) = b;
}

// ---------------- residual add + LayerNorm over D=1024 ----------------
__device__ __forceinline__ float block_sum_256(float v, float* sh)
{
#pragma unroll
    for (int o = 16; o; o >>= 1) v += __shfl_xor_sync(0xffffffffu, v, o);
    int w = threadIdx.x >> 5, lane = threadIdx.x & 31;
    if (lane == 0) sh[w] = v;
    __syncthreads();
    if (w == 0) {
        float t = (lane < 8) ? sh[lane] : 0.f;
#pragma unroll
        for (int o = 4; o; o >>= 1) t += __shfl_xor_sync(0xffffffffu, t, o);
        if (lane == 0) sh[0] = t;
    }
    __syncthreads();
    float r = sh[0];
    __syncthreads();
    return r;
}

__global__ void add_ln(const float* __restrict__ xa, const float* __restrict__ xb,
                       const float* __restrict__ g, const float* __restrict__ bt,
                       float* __restrict__ out)
{
    __shared__ float sh[8];
    int row = blockIdx.x;
    int tid = threadIdx.x;
    size_t base = (size_t)row * D_;
    float4 v = reinterpret_cast<const float4*>(xa + base)[tid];
    float4 r = reinterpret_cast<const float4*>(xb + base)[tid];
    v.x += r.x; v.y += r.y; v.z += r.z; v.w += r.w;
    float s = v.x + v.y + v.z + v.w;
    float mean = block_sum_256(s, sh) * (1.0f / D_);
    float d0 = v.x - mean, d1 = v.y - mean, d2 = v.z - mean, d3 = v.w - mean;
    float sq = d0 * d0 + d1 * d1 + d2 * d2 + d3 * d3;
    float var = block_sum_256(sq, sh) * (1.0f / D_);
    float rs = rsqrtf(var + 1e-12f);
    float4 gg = reinterpret_cast<const float4*>(g)[tid];
    float4 bb = reinterpret_cast<const float4*>(bt)[tid];
    float4 o;
    o.x = d0 * rs * gg.x + bb.x;
    o.y = d1 * rs * gg.y + bb.y;
    o.z = d2 * rs * gg.z + bb.z;
    o.w = d3 * rs * gg.w + bb.w;
    reinterpret_cast<float4*>(out + base)[tid] = o;
}

// ---------------- orchestration ----------------
extern "C" void kernel_launch(void* const* d_in, const int* in_sizes, int n_in,
                              void* d_out, int out_size)
{
    (void)in_sizes; (void)n_in; (void)out_size;
    const float* x   = (const float*)d_in[0];
    const float* Wq  = (const float*)d_in[1];
    const float* Wk  = (const float*)d_in[2];
    const float* Wv  = (const float*)d_in[3];
    const float* E   = (const float*)d_in[4];
    const float* F   = (const float*)d_in[5];
    const float* g1  = (const float*)d_in[6];
    const float* bl1 = (const float*)d_in[7];
    const float* W1  = (const float*)d_in[8];
    const float* bb1 = (const float*)d_in[9];
    const float* W2  = (const float*)d_in[10];
    const float* bb2 = (const float*)d_in[11];
    const float* g2  = (const float*)d_in[12];
    const float* bl2 = (const float*)d_in[13];
    float* out = (float*)d_out;

    float* S = nullptr;
    cudaGetSymbolAddress((void**)&S, g_scratch);
    float* qb  = S + OFF_Q;
    float* kb  = S + OFF_K;
    float* vb  = S + OFF_V;
    float* kp  = S + OFF_KP;
    float* vp  = S + OFF_VP;
    float* sc  = S + OFF_SC;
    float* t1  = S + OFF_T1;
    float* yb  = S + OFF_Y;
    float* hb  = S + OFF_HB;
    float* xb  = S + OFF_XB;
    float* kpp = S + OFF_KPP;
    float* vpp = S + OFF_VPP;
    float* wt  = S + OFF_WT;           // WqT | WkT | WvT, each L*D*D
    float* et  = S + OFF_ET;
    float* ft  = S + OFF_FT;
    float* kbt = S + OFF_KBT;
    float* vbt = S + OFF_VBT;
    float* vpt = S + OFF_VPT;
    float* w1r = S + OFF_W1R;
    float* w2r = S + OFF_W2R;

    const long long NDll  = (long long)N_ * D_;
    const long long KPDll = (long long)KP_ * D_;
    const long long NKPll = (long long)N_ * KP_;
    const size_t DD = (size_t)D_ * D_;

    const int SM128 = 2 * (128 * 32 * 4 + 128 * 32 * 4);  // 65536
    const int SM64  = 2 * (128 * 32 * 4 + 64 * 32 * 4);   // 49152
    cudaFuncSetAttribute((const void*)gemm_ls<128, 0, true,  false, true >, cudaFuncAttributeMaxDynamicSharedMemorySize, SM128);
    cudaFuncSetAttribute((const void*)gemm_ls<128, 0, false, false, false>, cudaFuncAttributeMaxDynamicSharedMemorySize, SM128);
    cudaFuncSetAttribute((const void*)gemm_ls<64,  0, false, false, false>, cudaFuncAttributeMaxDynamicSharedMemorySize, SM64);
    cudaFuncSetAttribute((const void*)gemm_ls<128, 2, true,  false, true >, cudaFuncAttributeMaxDynamicSharedMemorySize, SM128);
    cudaFuncSetAttribute((const void*)gemm_ls<128, 1, false, false, false>, cudaFuncAttributeMaxDynamicSharedMemorySize, SM128);

    dim3 tb(32, 8);

    // ---- once-per-launch pre-transforms (deterministic, idempotent) ----
    transpose_r<<<dim3(D_ / 32, D_ / 32, LL_), tb>>>(Wq, wt + 0 * LL_ * DD, D_, D_);
    transpose_r<<<dim3(D_ / 32, D_ / 32, LL_), tb>>>(Wk, wt + 1 * LL_ * DD, D_, D_);
    transpose_r<<<dim3(D_ / 32, D_ / 32, LL_), tb>>>(Wv, wt + 2 * LL_ * DD, D_, D_);
    transpose_r<<<dim3(KP_ / 32, N_ / 32, LL_), tb>>>(E, et, N_, KP_);
    transpose_r<<<dim3(KP_ / 32, N_ / 32, LL_), tb>>>(F, ft, N_, KP_);
    {
        int n4 = LL_ * FF_ * D_ / 4;
        round_copy4<<<(n4 + 255) / 256, 256>>>((const float4*)W1, (float4*)w1r, n4);
        round_copy4<<<(n4 + 255) / 256, 256>>>((const float4*)W2, (float4*)w2r, n4);
    }

    for (int l = 0; l < LL_; l++) {
        const float* xin = (l == 0) ? x : xb;

        // --- Q, K, V: A=x [8192][1024] raw, B=W^T [1024][1024] pre-rounded ---
        dim3 gQ(D_ / 128, (B_ * N_) / 128, 1);
        gemm_ls<128, 0, true, false, true><<<gQ, 256, SM128>>>(
            xin, wt + 0 * LL_ * DD + l * DD, qb, nullptr,
            D_, D_, D_, 0, 0, 0, 0, 0, 0, 0, 1, 1, D_);
        gemm_ls<128, 0, true, false, true><<<gQ, 256, SM128>>>(
            xin, wt + 1 * LL_ * DD + l * DD, kb, nullptr,
            D_, D_, D_, 0, 0, 0, 0, 0, 0, 0, 1, 1, D_);
        gemm_ls<128, 0, true, false, true><<<gQ, 256, SM128>>>(
            xin, wt + 2 * LL_ * DD + l * DD, vb, nullptr,
            D_, D_, D_, 0, 0, 0, 0, 0, 0, 0, 1, 1, D_);

        // --- kbT/vbT: [b][token][d] -> [b][d][token] ---
        transpose_r<<<dim3(D_ / 32, N_ / 32, B_), tb>>>(kb, kbt, N_, D_);
        transpose_r<<<dim3(D_ / 32, N_ / 32, B_), tb>>>(vb, vbt, N_, D_);

        // --- kp = E^T k, vp = F^T v : A=ET [256][4096], B=kbT [1024][4096], split-K ---
        dim3 gP(D_ / 128, KP_ / 128, B_ * SPLITK_);
        gemm_ls<128, 0, false, false, false><<<gP, 256, SM128>>>(
            et + (size_t)l * KP_ * N_, kbt, kpp, nullptr,
            N_, N_, D_,
            0, 0, 0, NDll, 0, KPDll, (long long)KPD_, 1, SPLITK_, N_);
        gemm_ls<128, 0, false, false, false><<<gP, 256, SM128>>>(
            ft + (size_t)l * KP_ * N_, vbt, vpp, nullptr,
            N_, N_, D_,
            0, 0, 0, NDll, 0, KPDll, (long long)KPD_, 1, SPLITK_, N_);
        reduce_slices<<<KPD_ / 256, 256>>>(kpp, kp, KPD_, SPLITK_, (long long)KPD_);
        reduce_slices<<<KPD_ / 256, 256>>>(vpp, vp, KPD_, SPLITK_, (long long)KPD_);

        // --- vpT: [b][e][d] -> [b][d][e] ---
        transpose_r<<<dim3(D_ / 32, KP_ / 32, B_), tb>>>(vp, vpt, KP_, D_);

        // --- scores: A=qb(head cols), B=kp(head cols), K=64, batched b*h ---
        dim3 gS(KP_ / 128, N_ / 128, B_ * H_);
        gemm_ls<128, 0, false, false, false><<<gS, 256, SM128>>>(
            qb, kp, sc, nullptr,
            D_, D_, KP_,
            HD_, NDll, HD_, KPDll, NKPll, (long long)H_ * NKPll, 0, H_, 1, HD_);

        // --- softmax (scale 1/8 folded; rounds output) ---
        softmax256<<<(B_ * H_ * N_) / 8, 256>>>(sc, B_ * H_ * N_);

        // --- attn = P VpT_h : A=sc [4096][256], B=vpT head rows [64][256] ---
        dim3 gA(1, N_ / 128, B_ * H_);
        gemm_ls<64, 0, false, false, false><<<gA, 128, SM64>>>(
            sc, vpt, t1, nullptr,
            KP_, KP_, D_,
            NKPll, (long long)H_ * NKPll, (long long)HD_ * KP_, (long long)D_ * KP_,
            HD_, NDll, 0, H_, 1, KP_);

        // --- y = LN(attn + x) ---
        add_ln<<<B_ * N_, 256>>>(t1, xin, g1 + (size_t)l * D_, bl1 + (size_t)l * D_, yb);

        // --- h = gelu(y W1^T + b1), output rounded ---
        dim3 gF1(FF_ / 128, (B_ * N_) / 128, 1);
        gemm_ls<128, 2, true, false, true><<<gF1, 256, SM128>>>(
            yb, w1r + (size_t)l * FF_ * D_, hb, bb1 + (size_t)l * FF_,
            D_, D_, FF_, 0, 0, 0, 0, 0, 0, 0, 1, 1, D_);

        // --- o = h W2^T + b2 ---
        dim3 gF2(D_ / 128, (B_ * N_) / 128, 1);
        gemm_ls<128, 1, false, false, false><<<gF2, 256, SM128>>>(
            hb, w2r + (size_t)l * D_ * FF_, t1, bb2 + (size_t)l * D_,
            FF_, FF_, D_, 0, 0, 0, 0, 0, 0, 0, 1, 1, FF_);

        // --- x_next = LN(o + y) ---
        add_ln<<<B_ * N_, 256>>>(t1, yb, g2 + (size_t)l * D_, bl2 + (size_t)l * D_,
                                 (l == LL_ - 1) ? out : xb);
    }
}

// round 8
// speedup vs baseline: 2.8189x; 1.0366x over previous
#include <cuda_runtime.h>
#include <math.h>
#include <stdint.h>

// ---------------- problem constants ----------------
#define LL_ 4
#define B_  2
#define N_  4096
#define D_  1024
#define H_  16
#define HD_ 64
#define KP_ 256
#define FF_ 4096

#define BND_  (B_*N_*D_)
#define KPD_  (B_*KP_*D_)
#define SCO_  (B_*H_*N_*KP_)
#define HBF_  (B_*N_*FF_)
#define SPLITK_ 8

// scratch layout (floats)
#define OFF_Q   ((size_t)0)
#define OFF_K   ((size_t)BND_)           // kbt  [b][d][token]
#define OFF_V   ((size_t)2*BND_)         // vbt  [b][d][token]
#define OFF_KP  ((size_t)3*BND_)         // kp   [b][e][d]
#define OFF_VP  (OFF_KP + KPD_)          // vpt  [b][d][e]
#define OFF_SC  (OFF_VP + KPD_)
#define OFF_T1  (OFF_SC + SCO_)
#define OFF_Y   (OFF_T1 + BND_)
#define OFF_HB  (OFF_Y  + BND_)
#define OFF_XB  (OFF_HB + HBF_)
#define OFF_KPP (OFF_XB + BND_)
#define OFF_VPP (OFF_KPP + (size_t)SPLITK_*KPD_)
#define OFF_WT  (OFF_VPP + (size_t)SPLITK_*KPD_)            // 3*L*D*D (WqT,WkT,WvT)
#define OFF_ET  (OFF_WT  + (size_t)3*LL_*D_*D_)
#define OFF_FT  (OFF_ET  + (size_t)LL_*KP_*N_)
#define OFF_W1R (OFF_FT  + (size_t)LL_*KP_*N_)
#define OFF_W2R (OFF_W1R + (size_t)LL_*FF_*D_)
#define SCRATCH_FLOATS (OFF_W2R + (size_t)LL_*D_*FF_)

__device__ float g_scratch[SCRATCH_FLOATS];

// ---------------- helpers ----------------
__device__ __forceinline__ float tf32r(float x) {
    unsigned u;
    asm("cvt.rna.tf32.f32 %0, %1;" : "=r"(u) : "f"(x));
    return __uint_as_float(u);
}
__device__ __forceinline__ void tf32r_u(uint32_t& x) {
    asm("cvt.rna.tf32.f32 %0, %1;" : "=r"(x) : "f"(__uint_as_float(x)));
}
__device__ __forceinline__ float gelu_exact(float x) {
    return 0.5f * x * (1.0f + erff(x * 0.70710678118654752f));
}
__device__ __forceinline__ uint32_t smem_u32(const void* p) {
    uint32_t a;
    asm("{ .reg .u64 t; cvta.to.shared.u64 t, %1; cvt.u32.u64 %0, t; }" : "=r"(a) : "l"(p));
    return a;
}
__device__ __forceinline__ void ldsm4(uint32_t r[4], uint32_t a) {
    asm volatile("ldmatrix.sync.aligned.m8n8.x4.shared.b16 {%0,%1,%2,%3}, [%4];"
                 : "=r"(r[0]), "=r"(r[1]), "=r"(r[2]), "=r"(r[3]) : "r"(a));
}
__device__ __forceinline__ void mma8(float c[4], const uint32_t a[4], uint32_t b0, uint32_t b1) {
    asm volatile(
        "mma.sync.aligned.m16n8k8.row.col.f32.tf32.tf32.f32 "
        "{%0,%1,%2,%3}, {%4,%5,%6,%7}, {%8,%9}, {%0,%1,%2,%3};"
        : "+f"(c[0]), "+f"(c[1]), "+f"(c[2]), "+f"(c[3])
        : "r"(a[0]), "r"(a[1]), "r"(a[2]), "r"(a[3]), "r"(b0), "r"(b1));
}
#define CP16(dst, src) asm volatile("cp.async.cg.shared.global [%0], [%1], 16;" :: "r"(dst), "l"(src))
#define CP_COMMIT()    asm volatile("cp.async.commit_group;" ::: "memory")
#define CP_WAIT(N)     asm volatile("cp.async.wait_group %0;" :: "n"(N) : "memory")

// ---------------- tf32 mma.sync GEMM: swizzled smem + ldmatrix + cp.async ----
// C(M,N) = A(M,K)*B^T(N,K): A gmem [m][k] (lda), B gmem [n][k] (ldb). BK=32.
// Warp tile 32x64; warp grid WGM=BM/32 (m) x BN/64 (n).
// smem tiles row-major 128B rows, 16B-unit xor swizzle u^(row&7).
// CA/CB: tf32-round A/B fragments. RO: round outputs.
// EPI: 0 none, 1 +bias, 2 +bias+gelu. SOFTM: fused row softmax (needs BN==N==256).
template<int BM, int BN, int EPI, bool CA, bool CB, bool RO, bool SOFTM>
__global__ void __launch_bounds__((BM/32)*(BN/64)*32, ((BM/32)*(BN/64)*32) == 256 ? 2 : 4)
gemm_ls(const float* __restrict__ Ag, const float* __restrict__ Bg,
        float* __restrict__ Cg, const float* __restrict__ bias,
        int lda, int ldb, int ldc,
        long long sAi, long long sAo, long long sBi, long long sBo,
        long long sCi, long long sCo, long long sCk,
        int binner, int splitK, int Kd)
{
    constexpr int BK = 32;
    constexpr int WGM = BM / 32;
    constexpr int THREADS = WGM * (BN / 64) * 32;
    constexpr int ABY = BM * BK * 4;
    constexpr int BBY = BN * BK * 4;
    constexpr int STG = ABY + BBY;

    extern __shared__ char sm[];
    const uint32_t smb = smem_u32(sm);
    const int tid = threadIdx.x, w = tid >> 5, lane = tid & 31;
    const int l7 = lane & 7, sel = lane >> 3;

    const int z  = blockIdx.z;
    const int zk = z % splitK;
    const int zb = z / splitK;
    const int zi = zb % binner;
    const int zo = zb / binner;
    const float* A  = Ag + zi * sAi + zo * sAo;
    const float* Bp = Bg + zi * sBi + zo * sBo;
    float*       C  = Cg + zi * sCi + zo * sCo + (long long)zk * sCk;

    const int m0 = blockIdx.y * BM;
    const int n0 = blockIdx.x * BN;
    const int kPer = Kd / splitK;
    const int kbeg = zk * kPer;
    const int ntiles = kPer / BK;

    const int wmB = (w % WGM) * 32;
    const int wnB = (w / WGM) * 64;
    const int lr = lane >> 2, lc = lane & 3;

    float acc[2][8][4];
#pragma unroll
    for (int i = 0; i < 2; i++)
#pragma unroll
        for (int j = 0; j < 8; j++)
#pragma unroll
            for (int q = 0; q < 4; q++) acc[i][j][q] = 0.f;

    auto stage = [&](int s, int kb) {
        uint32_t sa = smb + (uint32_t)(s * STG);
        uint32_t sb2 = sa + ABY;
#pragma unroll
        for (int t = 0; t < (BM * BK / 4) / THREADS; t++) {
            int i = tid + t * THREADS;
            int m = i >> 3, kq = i & 7;
            uint32_t dst = sa + (uint32_t)(m * 128 + ((kq ^ (m & 7)) << 4));
            const void* src = (const void*)(A + (size_t)(m0 + m) * lda + kb + kq * 4);
            CP16(dst, src);
        }
#pragma unroll
        for (int t = 0; t < (BN * BK / 4) / THREADS; t++) {
            int i = tid + t * THREADS;
            int n = i >> 3, kq = i & 7;
            uint32_t dst = sb2 + (uint32_t)(n * 128 + ((kq ^ (n & 7)) << 4));
            const void* src = (const void*)(Bp + (size_t)(n0 + n) * ldb + kb + kq * 4);
            CP16(dst, src);
        }
        CP_COMMIT();
    };

    auto compute = [&](int s) {
        uint32_t sa = smb + (uint32_t)(s * STG);
        uint32_t sb2 = sa + ABY;
        uint32_t arow0 = sa + (uint32_t)((wmB + ((sel & 1) << 3) + l7) * 128);
        uint32_t arow1 = arow0 + 16 * 128;
        uint32_t brow[4];
#pragma unroll
        for (int p = 0; p < 4; p++)
            brow[p] = sb2 + (uint32_t)((wnB + p * 16 + ((sel >> 1) << 3) + l7) * 128);
        const int aub = sel >> 1, bub = sel & 1;
#pragma unroll
        for (int kt = 0; kt < 4; kt++) {
            uint32_t a[2][4], b[4][4];
            uint32_t au = (uint32_t)(((2 * kt + aub) ^ l7) << 4);
            uint32_t bu = (uint32_t)(((2 * kt + bub) ^ l7) << 4);
            ldsm4(a[0], arow0 + au);
            ldsm4(a[1], arow1 + au);
#pragma unroll
            for (int p = 0; p < 4; p++) ldsm4(b[p], brow[p] + bu);
            if constexpr (CA) {
#pragma unroll
                for (int mt = 0; mt < 2; mt++)
#pragma unroll
                    for (int j = 0; j < 4; j++) tf32r_u(a[mt][j]);
            }
            if constexpr (CB) {
#pragma unroll
                for (int p = 0; p < 4; p++)
#pragma unroll
                    for (int j = 0; j < 4; j++) tf32r_u(b[p][j]);
            }
#pragma unroll
            for (int mt = 0; mt < 2; mt++)
#pragma unroll
                for (int p = 0; p < 4; p++) {
                    mma8(acc[mt][2 * p],     a[mt], b[p][0], b[p][1]);
                    mma8(acc[mt][2 * p + 1], a[mt], b[p][2], b[p][3]);
                }
        }
    };

    stage(0, kbeg);
    for (int t = 0; t < ntiles; t++) {
        int s = t & 1;
        if (t + 1 < ntiles) {
            stage(s ^ 1, kbeg + (t + 1) * BK);
            CP_WAIT(1);
        } else {
            CP_WAIT(0);
        }
        __syncthreads();
        compute(s);
        __syncthreads();
    }

    if constexpr (SOFTM) {
        // fused softmax over the CTA's full BN(=256)-wide rows. scale 1/8 folded.
        float* red = reinterpret_cast<float*>(sm);   // stage smem reused: [4 nwarp][BM rows]
        const int nw = w / WGM;
        const int rbase = wmB + lr;
#pragma unroll
        for (int mt = 0; mt < 2; mt++)
#pragma unroll
            for (int nt = 0; nt < 8; nt++)
#pragma unroll
                for (int q = 0; q < 4; q++) acc[mt][nt][q] *= 0.125f;
        float mx[2][2];
#pragma unroll
        for (int mt = 0; mt < 2; mt++)
#pragma unroll
            for (int h = 0; h < 2; h++) {
                float m = -3.4e38f;
#pragma unroll
                for (int nt = 0; nt < 8; nt++)
                    m = fmaxf(m, fmaxf(acc[mt][nt][2 * h], acc[mt][nt][2 * h + 1]));
                mx[mt][h] = m;
            }
#pragma unroll
        for (int off = 1; off <= 2; off <<= 1)
#pragma unroll
            for (int mt = 0; mt < 2; mt++)
#pragma unroll
                for (int h = 0; h < 2; h++)
                    mx[mt][h] = fmaxf(mx[mt][h], __shfl_xor_sync(0xffffffffu, mx[mt][h], off));
        if (lc == 0) {
#pragma unroll
            for (int mt = 0; mt < 2; mt++)
#pragma unroll
                for (int h = 0; h < 2; h++)
                    red[nw * BM + rbase + mt * 16 + h * 8] = mx[mt][h];
        }
        __syncthreads();
        float mf[2][2];
#pragma unroll
        for (int mt = 0; mt < 2; mt++)
#pragma unroll
            for (int h = 0; h < 2; h++) {
                int rr = rbase + mt * 16 + h * 8;
                mf[mt][h] = fmaxf(fmaxf(red[rr], red[BM + rr]),
                                  fmaxf(red[2 * BM + rr], red[3 * BM + rr]));
            }
        __syncthreads();
        float sm2[2][2] = {{0.f, 0.f}, {0.f, 0.f}};
#pragma unroll
        for (int mt = 0; mt < 2; mt++)
#pragma unroll
            for (int nt = 0; nt < 8; nt++) {
                acc[mt][nt][0] = expf(acc[mt][nt][0] - mf[mt][0]);
                acc[mt][nt][1] = expf(acc[mt][nt][1] - mf[mt][0]);
                acc[mt][nt][2] = expf(acc[mt][nt][2] - mf[mt][1]);
                acc[mt][nt][3] = expf(acc[mt][nt][3] - mf[mt][1]);
                sm2[mt][0] += acc[mt][nt][0] + acc[mt][nt][1];
                sm2[mt][1] += acc[mt][nt][2] + acc[mt][nt][3];
            }
#pragma unroll
        for (int off = 1; off <= 2; off <<= 1)
#pragma unroll
            for (int mt = 0; mt < 2; mt++)
#pragma unroll
                for (int h = 0; h < 2; h++)
                    sm2[mt][h] += __shfl_xor_sync(0xffffffffu, sm2[mt][h], off);
        if (lc == 0) {
#pragma unroll
            for (int mt = 0; mt < 2; mt++)
#pragma unroll
                for (int h = 0; h < 2; h++)
                    red[nw * BM + rbase + mt * 16 + h * 8] = sm2[mt][h];
        }
        __syncthreads();
        float ri[2][2];
#pragma unroll
        for (int mt = 0; mt < 2; mt++)
#pragma unroll
            for (int h = 0; h < 2; h++) {
                int rr = rbase + mt * 16 + h * 8;
                ri[mt][h] = 1.0f / (red[rr] + red[BM + rr] + red[2 * BM + rr] + red[3 * BM + rr]);
            }
#pragma unroll
        for (int mt = 0; mt < 2; mt++)
#pragma unroll
            for (int nt = 0; nt < 8; nt++) {
                int r = m0 + wmB + mt * 16 + lr;
                int c = n0 + wnB + nt * 8 + lc * 2;
                float v0 = tf32r(acc[mt][nt][0] * ri[mt][0]);
                float v1 = tf32r(acc[mt][nt][1] * ri[mt][0]);
                float v2 = tf32r(acc[mt][nt][2] * ri[mt][1]);
                float v3 = tf32r(acc[mt][nt][3] * ri[mt][1]);
                *reinterpret_cast<float2*>(C + (size_t)r * ldc + c)       = make_float2(v0, v1);
                *reinterpret_cast<float2*>(C + (size_t)(r + 8) * ldc + c) = make_float2(v2, v3);
            }
        return;
    }

    // ---- normal epilogue ----
#pragma unroll
    for (int mt = 0; mt < 2; mt++) {
#pragma unroll
        for (int nt = 0; nt < 8; nt++) {
            int r = m0 + wmB + mt * 16 + lr;
            int c = n0 + wnB + nt * 8 + lc * 2;
            float v0 = acc[mt][nt][0], v1 = acc[mt][nt][1];
            float v2 = acc[mt][nt][2], v3 = acc[mt][nt][3];
            if constexpr (EPI >= 1) {
                float bc0 = bias[c], bc1 = bias[c + 1];
                v0 += bc0; v1 += bc1; v2 += bc0; v3 += bc1;
            }
            if constexpr (EPI == 2) {
                v0 = gelu_exact(v0); v1 = gelu_exact(v1);
                v2 = gelu_exact(v2); v3 = gelu_exact(v3);
            }
            if constexpr (RO) {
                v0 = tf32r(v0); v1 = tf32r(v1); v2 = tf32r(v2); v3 = tf32r(v3);
            }
            *reinterpret_cast<float2*>(C + (size_t)r * ldc + c)       = make_float2(v0, v1);
            *reinterpret_cast<float2*>(C + (size_t)(r + 8) * ldc + c) = make_float2(v2, v3);
        }
    }
}

// ---------------- batched 32x32 tiled transpose (tf32-rounds output) --------
__global__ void transpose_r(const float* __restrict__ in, float* __restrict__ out,
                            int R, int C)
{
    __shared__ float t[32][33];
    long long zoff = (long long)blockIdx.z * R * C;
    int c0 = blockIdx.x * 32, r0 = blockIdx.y * 32;
    int x = threadIdx.x, y = threadIdx.y;
#pragma unroll
    for (int i = 0; i < 32; i += 8)
        t[y + i][x] = in[zoff + (long long)(r0 + y + i) * C + (c0 + x)];
    __syncthreads();
#pragma unroll
    for (int i = 0; i < 32; i += 8)
        out[zoff + (long long)(c0 + y + i) * R + (r0 + x)] = tf32r(t[x][y + i]);
}

// ---------------- elementwise tf32-round copy ----------------
__global__ void round_copy4(const float4* __restrict__ in, float4* __restrict__ out, int n4)
{
    int i = blockIdx.x * blockDim.x + threadIdx.x;
    if (i < n4) {
        float4 v = in[i];
        v.x = tf32r(v.x); v.y = tf32r(v.y); v.z = tf32r(v.z); v.w = tf32r(v.w);
        out[i] = v;
    }
}

// ---------------- split-K reduce (deterministic; rounds output) -------------
__global__ void reduce_slices(const float* __restrict__ part, float* __restrict__ out,
                              int n, int slices, long long stride)
{
    int i = blockIdx.x * blockDim.x + threadIdx.x;
    if (i < n) {
        float s = 0.f;
        for (int t = 0; t < slices; t++) s += part[i + (long long)t * stride];
        out[i] = tf32r(s);
    }
}

// ---------------- residual add + LayerNorm over D=1024 ----------------
__device__ __forceinline__ float block_sum_256(float v, float* sh)
{
#pragma unroll
    for (int o = 16; o; o >>= 1) v += __shfl_xor_sync(0xffffffffu, v, o);
    int w = threadIdx.x >> 5, lane = threadIdx.x & 31;
    if (lane == 0) sh[w] = v;
    __syncthreads();
    if (w == 0) {
        float t = (lane < 8) ? sh[lane] : 0.f;
#pragma unroll
        for (int o = 4; o; o >>= 1) t += __shfl_xor_sync(0xffffffffu, t, o);
        if (lane == 0) sh[0] = t;
    }
    __syncthreads();
    float r = sh[0];
    __syncthreads();
    return r;
}

__global__ void add_ln(const float* __restrict__ xa, const float* __restrict__ xb,
                       const float* __restrict__ g, const float* __restrict__ bt,
                       float* __restrict__ out)
{
    __shared__ float sh[8];
    int row = blockIdx.x;
    int tid = threadIdx.x;
    size_t base = (size_t)row * D_;
    float4 v = reinterpret_cast<const float4*>(xa + base)[tid];
    float4 r = reinterpret_cast<const float4*>(xb + base)[tid];
    v.x += r.x; v.y += r.y; v.z += r.z; v.w += r.w;
    float s = v.x + v.y + v.z + v.w;
    float mean = block_sum_256(s, sh) * (1.0f / D_);
    float d0 = v.x - mean, d1 = v.y - mean, d2 = v.z - mean, d3 = v.w - mean;
    float sq = d0 * d0 + d1 * d1 + d2 * d2 + d3 * d3;
    float var = block_sum_256(sq, sh) * (1.0f / D_);
    float rs = rsqrtf(var + 1e-12f);
    float4 gg = reinterpret_cast<const float4*>(g)[tid];
    float4 bb = reinterpret_cast<const float4*>(bt)[tid];
    float4 o;
    o.x = d0 * rs * gg.x + bb.x;
    o.y = d1 * rs * gg.y + bb.y;
    o.z = d2 * rs * gg.z + bb.z;
    o.w = d3 * rs * gg.w + bb.w;
    reinterpret_cast<float4*>(out + base)[tid] = o;
}

// ---------------- orchestration ----------------
extern "C" void kernel_launch(void* const* d_in, const int* in_sizes, int n_in,
                              void* d_out, int out_size)
{
    (void)in_sizes; (void)n_in; (void)out_size;
    const float* x   = (const float*)d_in[0];
    const float* Wq  = (const float*)d_in[1];
    const float* Wk  = (const float*)d_in[2];
    const float* Wv  = (const float*)d_in[3];
    const float* E   = (const float*)d_in[4];
    const float* F   = (const float*)d_in[5];
    const float* g1  = (const float*)d_in[6];
    const float* bl1 = (const float*)d_in[7];
    const float* W1  = (const float*)d_in[8];
    const float* bb1 = (const float*)d_in[9];
    const float* W2  = (const float*)d_in[10];
    const float* bb2 = (const float*)d_in[11];
    const float* g2  = (const float*)d_in[12];
    const float* bl2 = (const float*)d_in[13];
    float* out = (float*)d_out;

    float* S = nullptr;
    cudaGetSymbolAddress((void**)&S, g_scratch);
    float* qb  = S + OFF_Q;
    float* kbt = S + OFF_K;
    float* vbt = S + OFF_V;
    float* kp  = S + OFF_KP;
    float* vpt = S + OFF_VP;
    float* sc  = S + OFF_SC;
    float* t1  = S + OFF_T1;
    float* yb  = S + OFF_Y;
    float* hb  = S + OFF_HB;
    float* xb  = S + OFF_XB;
    float* kpp = S + OFF_KPP;
    float* wt  = S + OFF_WT;
    float* et  = S + OFF_ET;
    float* w1r = S + OFF_W1R;
    float* w2r = S + OFF_W2R;

    const long long NDll  = (long long)N_ * D_;
    const long long KPDll = (long long)KP_ * D_;
    const long long NKPll = (long long)N_ * KP_;
    const long long LLDD  = (long long)LL_ * D_ * D_;
    const size_t DD = (size_t)D_ * D_;

    const int SM128 = 2 * ((128 + 128) * 32 * 4);   // 65536
    const int SMSC  = 2 * ((64 + 256) * 32 * 4);    // 81920
    const int SM64  = 2 * ((128 + 64) * 32 * 4);    // 49152
    cudaFuncSetAttribute((const void*)gemm_ls<128, 128, 0, true,  false, true,  false>, cudaFuncAttributeMaxDynamicSharedMemorySize, SM128);
    cudaFuncSetAttribute((const void*)gemm_ls<128, 128, 0, false, true,  true,  false>, cudaFuncAttributeMaxDynamicSharedMemorySize, SM128);
    cudaFuncSetAttribute((const void*)gemm_ls<128, 128, 0, false, false, false, false>, cudaFuncAttributeMaxDynamicSharedMemorySize, SM128);
    cudaFuncSetAttribute((const void*)gemm_ls<64,  256, 0, false, false, false, true >, cudaFuncAttributeMaxDynamicSharedMemorySize, SMSC);
    cudaFuncSetAttribute((const void*)gemm_ls<128, 64,  0, false, false, false, false>, cudaFuncAttributeMaxDynamicSharedMemorySize, SM64);
    cudaFuncSetAttribute((const void*)gemm_ls<128, 128, 2, true,  false, true,  false>, cudaFuncAttributeMaxDynamicSharedMemorySize, SM128);
    cudaFuncSetAttribute((const void*)gemm_ls<128, 128, 1, false, false, false, false>, cudaFuncAttributeMaxDynamicSharedMemorySize, SM128);

    dim3 tb(32, 8);

    // ---- once-per-launch pre-transforms (deterministic, idempotent) ----
    transpose_r<<<dim3(D_ / 32, D_ / 32, LL_), tb>>>(Wq, wt + 0 * LL_ * DD, D_, D_);
    transpose_r<<<dim3(D_ / 32, D_ / 32, LL_), tb>>>(Wk, wt + 1 * LL_ * DD, D_, D_);
    transpose_r<<<dim3(D_ / 32, D_ / 32, LL_), tb>>>(Wv, wt + 2 * LL_ * DD, D_, D_);
    transpose_r<<<dim3(KP_ / 32, N_ / 32, LL_), tb>>>(E, et, N_, KP_);
    transpose_r<<<dim3(KP_ / 32, N_ / 32, LL_), tb>>>(F, et + (size_t)LL_ * KP_ * N_, N_, KP_);
    {
        int n4 = LL_ * FF_ * D_ / 4;
        round_copy4<<<(n4 + 255) / 256, 256>>>((const float4*)W1, (float4*)w1r, n4);
        round_copy4<<<(n4 + 255) / 256, 256>>>((const float4*)W2, (float4*)w2r, n4);
    }

    for (int l = 0; l < LL_; l++) {
        const float* xin = (l == 0) ? x : xb;

        // --- q = x WqT : [8192,1024], A=x raw, B=wqT pre-rounded ---
        dim3 gQ(D_ / 128, (B_ * N_) / 128, 1);
        gemm_ls<128, 128, 0, true, false, true, false><<<gQ, 256, SM128>>>(
            xin, wt + 0 * LL_ * DD + l * DD, qb, nullptr,
            D_, D_, D_, 0, 0, 0, 0, 0, 0, 0, 1, 1, D_);

        // --- kbt/vbt direct: C[d][token] = W^T x^T. zo: {Wk,Wv}, zi: batch ---
        dim3 gKV(N_ / 128, D_ / 128, 2 * B_);
        gemm_ls<128, 128, 0, false, true, true, false><<<gKV, 256, SM128>>>(
            wt + 1 * LL_ * DD + l * DD, xin, kbt, nullptr,
            D_, D_, N_,
            0, LLDD, NDll, 0, NDll, (long long)BND_, 0, B_, 1, D_);

        // --- kpp/vpp: kp=E^T k -> [e][d]; vptp = v^T F -> [d][e]. split-K=8 ---
        // zo=0: A=et[e][t], B=kbt[d][t], C=kpp[e][d]
        // zo=1: A=vbt[d][t], B=ft[e][t], C=vpp[d][e]  (A/B swapped roles via strides)
        // Implemented as two launches kept distinct shapes; merged via zo on matching dims:
        dim3 gP1(D_ / 128, KP_ / 128, B_ * SPLITK_);
        gemm_ls<128, 128, 0, false, false, false, false><<<gP1, 256, SM128>>>(
            et + (size_t)l * KP_ * N_, kbt, kpp, nullptr,
            N_, N_, D_,
            0, 0, NDll, 0, KPDll, 0, (long long)KPD_, B_, SPLITK_, N_);
        dim3 gP2(KP_ / 128, D_ / 128, B_ * SPLITK_);
        gemm_ls<128, 128, 0, false, false, false, false><<<gP2, 256, SM128>>>(
            vbt, et + (size_t)(LL_ + l) * KP_ * N_, kpp + (size_t)SPLITK_ * KPD_, nullptr,
            N_, N_, KP_,
            NDll, 0, 0, 0, KPDll, 0, (long long)KPD_, B_, SPLITK_, N_);
        reduce_slices<<<KPD_ / 256, 256>>>(kpp, kp, KPD_, SPLITK_, (long long)KPD_);
        reduce_slices<<<KPD_ / 256, 256>>>(kpp + (size_t)SPLITK_ * KPD_, vpt, KPD_, SPLITK_, (long long)KPD_);

        // --- scores + fused softmax: BM=64, BN=256 (full rows), batched b*h ---
        dim3 gS(1, N_ / 64, B_ * H_);
        gemm_ls<64, 256, 0, false, false, false, true><<<gS, 256, SMSC>>>(
            qb, kp, sc, nullptr,
            D_, D_, KP_,
            HD_, NDll, HD_, KPDll, NKPll, (long long)H_ * NKPll, 0, H_, 1, HD_);

        // --- attn = P VpT_h : A=sc [4096][256], B=vpt head rows [64][256] ---
        dim3 gA(1, N_ / 128, B_ * H_);
        gemm_ls<128, 64, 0, false, false, false, false><<<gA, 128, SM64>>>(
            sc, vpt, t1, nullptr,
            KP_, KP_, D_,
            NKPll, (long long)H_ * NKPll, (long long)HD_ * KP_, (long long)D_ * KP_,
            HD_, NDll, 0, H_, 1, KP_);

        // --- y = LN(attn + x) ---
        add_ln<<<B_ * N_, 256>>>(t1, xin, g1 + (size_t)l * D_, bl1 + (size_t)l * D_, yb);

        // --- h = gelu(y W1^T + b1), output rounded ---
        dim3 gF1(FF_ / 128, (B_ * N_) / 128, 1);
        gemm_ls<128, 128, 2, true, false, true, false><<<gF1, 256, SM128>>>(
            yb, w1r + (size_t)l * FF_ * D_, hb, bb1 + (size_t)l * FF_,
            D_, D_, FF_, 0, 0, 0, 0, 0, 0, 0, 1, 1, D_);

        // --- o = h W2^T + b2 ---
        dim3 gF2(D_ / 128, (B_ * N_) / 128, 1);
        gemm_ls<128, 128, 1, false, false, false, false><<<gF2, 256, SM128>>>(
            hb, w2r + (size_t)l * D_ * FF_, t1, bb2 + (size_t)l * D_,
            FF_, FF_, D_, 0, 0, 0, 0, 0, 0, 0, 1, 1, FF_);

        // --- x_next = LN(o + y) ---
        add_ln<<<B_ * N_, 256>>>(t1, yb, g2 + (size_t)l * D_, bl2 + (size_t)l * D_,
                                 (l == LL_ - 1) ? out : xb);
    }
}

// round 9
// speedup vs baseline: 2.8458x; 1.0095x over previous
#include <cuda_runtime.h>
#include <math.h>
#include <stdint.h>

// ---------------- problem constants ----------------
#define LL_ 4
#define B_  2
#define N_  4096
#define D_  1024
#define H_  16
#define HD_ 64
#define KP_ 256
#define FF_ 4096

#define BND_  (B_*N_*D_)
#define KPD_  (B_*KP_*D_)
#define SCO_  (B_*H_*N_*KP_)
#define HBF_  (B_*N_*FF_)
#define SPLITK_ 8

// scratch layout (floats)
#define OFF_Q   ((size_t)0)
#define OFF_K   ((size_t)BND_)           // kbt  [b][d][token]
#define OFF_V   ((size_t)2*BND_)         // vbt  [b][d][token]
#define OFF_KP  ((size_t)3*BND_)         // kp   [b][e][d]
#define OFF_VP  (OFF_KP + KPD_)          // vpt  [b][d][e]
#define OFF_SC  (OFF_VP + KPD_)
#define OFF_T1  (OFF_SC + SCO_)
#define OFF_Y   (OFF_T1 + BND_)
#define OFF_HB  (OFF_Y  + BND_)
#define OFF_XB  (OFF_HB + HBF_)
#define OFF_KPP (OFF_XB + BND_)
#define OFF_VPP (OFF_KPP + (size_t)SPLITK_*KPD_)
#define OFF_WT  (OFF_VPP + (size_t)SPLITK_*KPD_)            // 3*L*D*D (WqT,WkT,WvT)
#define OFF_ET  (OFF_WT  + (size_t)3*LL_*D_*D_)
#define OFF_FT  (OFF_ET  + (size_t)LL_*KP_*N_)
#define OFF_W1R (OFF_FT  + (size_t)LL_*KP_*N_)
#define OFF_W2R (OFF_W1R + (size_t)LL_*FF_*D_)
#define SCRATCH_FLOATS (OFF_W2R + (size_t)LL_*D_*FF_)

__device__ float g_scratch[SCRATCH_FLOATS];

// ---------------- helpers ----------------
__device__ __forceinline__ float tf32r(float x) {
    unsigned u;
    asm("cvt.rna.tf32.f32 %0, %1;" : "=r"(u) : "f"(x));
    return __uint_as_float(u);
}
__device__ __forceinline__ void tf32r_u(uint32_t& x) {
    asm("cvt.rna.tf32.f32 %0, %1;" : "=r"(x) : "f"(__uint_as_float(x)));
}
__device__ __forceinline__ float gelu_exact(float x) {
    return 0.5f * x * (1.0f + erff(x * 0.70710678118654752f));
}
__device__ __forceinline__ uint32_t smem_u32(const void* p) {
    uint32_t a;
    asm("{ .reg .u64 t; cvta.to.shared.u64 t, %1; cvt.u32.u64 %0, t; }" : "=r"(a) : "l"(p));
    return a;
}
__device__ __forceinline__ void ldsm4(uint32_t r[4], uint32_t a) {
    asm volatile("ldmatrix.sync.aligned.m8n8.x4.shared.b16 {%0,%1,%2,%3}, [%4];"
                 : "=r"(r[0]), "=r"(r[1]), "=r"(r[2]), "=r"(r[3]) : "r"(a));
}
__device__ __forceinline__ void mma8(float c[4], const uint32_t a[4], uint32_t b0, uint32_t b1) {
    asm volatile(
        "mma.sync.aligned.m16n8k8.row.col.f32.tf32.tf32.f32 "
        "{%0,%1,%2,%3}, {%4,%5,%6,%7}, {%8,%9}, {%0,%1,%2,%3};"
        : "+f"(c[0]), "+f"(c[1]), "+f"(c[2]), "+f"(c[3])
        : "r"(a[0]), "r"(a[1]), "r"(a[2]), "r"(a[3]), "r"(b0), "r"(b1));
}
#define CP16(dst, src) asm volatile("cp.async.cg.shared.global [%0], [%1], 16;" :: "r"(dst), "l"(src))
#define CP_COMMIT()    asm volatile("cp.async.commit_group;" ::: "memory")
#define CP_WAIT(N)     asm volatile("cp.async.wait_group %0;" :: "n"(N) : "memory")

// ---------------- tf32 mma.sync GEMM: swizzled smem + ldmatrix + cp.async ----
// C(M,N) = A(M,K)*B^T(N,K): A gmem [m][k] (lda), B gmem [n][k] (ldb). BK=32.
// Warp tile WM x 64; warp grid WGM=BM/WM (m) x BN/64 (n).
// smem tiles row-major 128B rows, 16B-unit xor swizzle u^(row&7).
// CA/CB: tf32-round A/B fragments. RO: round outputs.
// EPI: 0 none, 1 +bias, 2 +bias+gelu. SOFTM: fused row softmax (needs BN==N==256).
template<int BM, int BN, int WM, int EPI, bool CA, bool CB, bool RO, bool SOFTM>
__global__ void __launch_bounds__((BM/WM)*(BN/64)*32, 2)
gemm_ls(const float* __restrict__ Ag, const float* __restrict__ Bg,
        float* __restrict__ Cg, const float* __restrict__ bias,
        int lda, int ldb, int ldc,
        long long sAi, long long sAo, long long sBi, long long sBo,
        long long sCi, long long sCo, long long sCk,
        int binner, int splitK, int Kd)
{
    constexpr int BK = 32;
    constexpr int WGM = BM / WM;
    constexpr int MT  = WM / 16;
    constexpr int THREADS = WGM * (BN / 64) * 32;
    constexpr int ABY = BM * BK * 4;
    constexpr int BBY = BN * BK * 4;
    constexpr int STG = ABY + BBY;

    extern __shared__ char sm[];
    const uint32_t smb = smem_u32(sm);
    const int tid = threadIdx.x, w = tid >> 5, lane = tid & 31;
    const int l7 = lane & 7, sel = lane >> 3;

    const int z  = blockIdx.z;
    const int zk = z % splitK;
    const int zb = z / splitK;
    const int zi = zb % binner;
    const int zo = zb / binner;
    const float* A  = Ag + zi * sAi + zo * sAo;
    const float* Bp = Bg + zi * sBi + zo * sBo;
    float*       C  = Cg + zi * sCi + zo * sCo + (long long)zk * sCk;

    const int m0 = blockIdx.y * BM;
    const int n0 = blockIdx.x * BN;
    const int kPer = Kd / splitK;
    const int kbeg = zk * kPer;
    const int ntiles = kPer / BK;

    const int wmB = (w % WGM) * WM;
    const int wnB = (w / WGM) * 64;
    const int lr = lane >> 2, lc = lane & 3;

    float acc[MT][8][4];
#pragma unroll
    for (int i = 0; i < MT; i++)
#pragma unroll
        for (int j = 0; j < 8; j++)
#pragma unroll
            for (int q = 0; q < 4; q++) acc[i][j][q] = 0.f;

    auto stage = [&](int s, int kb) {
        uint32_t sa = smb + (uint32_t)(s * STG);
        uint32_t sb2 = sa + ABY;
#pragma unroll
        for (int t = 0; t < (BM * BK / 4) / THREADS; t++) {
            int i = tid + t * THREADS;
            int m = i >> 3, kq = i & 7;
            uint32_t dst = sa + (uint32_t)(m * 128 + ((kq ^ (m & 7)) << 4));
            const void* src = (const void*)(A + (size_t)(m0 + m) * lda + kb + kq * 4);
            CP16(dst, src);
        }
#pragma unroll
        for (int t = 0; t < (BN * BK / 4) / THREADS; t++) {
            int i = tid + t * THREADS;
            int n = i >> 3, kq = i & 7;
            uint32_t dst = sb2 + (uint32_t)(n * 128 + ((kq ^ (n & 7)) << 4));
            const void* src = (const void*)(Bp + (size_t)(n0 + n) * ldb + kb + kq * 4);
            CP16(dst, src);
        }
        CP_COMMIT();
    };

    auto compute = [&](int s) {
        uint32_t sa = smb + (uint32_t)(s * STG);
        uint32_t sb2 = sa + ABY;
        uint32_t arow[MT];
#pragma unroll
        for (int mt = 0; mt < MT; mt++)
            arow[mt] = sa + (uint32_t)((wmB + mt * 16 + ((sel & 1) << 3) + l7) * 128);
        uint32_t brow[4];
#pragma unroll
        for (int p = 0; p < 4; p++)
            brow[p] = sb2 + (uint32_t)((wnB + p * 16 + ((sel >> 1) << 3) + l7) * 128);
        const int aub = sel >> 1, bub = sel & 1;
#pragma unroll
        for (int kt = 0; kt < 4; kt++) {
            uint32_t a[MT][4], b[4][4];
            uint32_t au = (uint32_t)(((2 * kt + aub) ^ l7) << 4);
            uint32_t bu = (uint32_t)(((2 * kt + bub) ^ l7) << 4);
#pragma unroll
            for (int mt = 0; mt < MT; mt++) ldsm4(a[mt], arow[mt] + au);
#pragma unroll
            for (int p = 0; p < 4; p++) ldsm4(b[p], brow[p] + bu);
            if constexpr (CA) {
#pragma unroll
                for (int mt = 0; mt < MT; mt++)
#pragma unroll
                    for (int j = 0; j < 4; j++) tf32r_u(a[mt][j]);
            }
            if constexpr (CB) {
#pragma unroll
                for (int p = 0; p < 4; p++)
#pragma unroll
                    for (int j = 0; j < 4; j++) tf32r_u(b[p][j]);
            }
#pragma unroll
            for (int mt = 0; mt < MT; mt++)
#pragma unroll
                for (int p = 0; p < 4; p++) {
                    mma8(acc[mt][2 * p],     a[mt], b[p][0], b[p][1]);
                    mma8(acc[mt][2 * p + 1], a[mt], b[p][2], b[p][3]);
                }
        }
    };

    stage(0, kbeg);
    for (int t = 0; t < ntiles; t++) {
        int s = t & 1;
        if (t + 1 < ntiles) {
            stage(s ^ 1, kbeg + (t + 1) * BK);
            CP_WAIT(1);
        } else {
            CP_WAIT(0);
        }
        __syncthreads();
        compute(s);
        __syncthreads();
    }

    if constexpr (SOFTM) {
        // fused softmax over the CTA's full BN(=256)-wide rows. scale 1/8 folded.
        float* red = reinterpret_cast<float*>(sm);   // stage smem reused: [nwarps][BM rows]
        const int nw = w / WGM;
        const int rbase = wmB + lr;
#pragma unroll
        for (int mt = 0; mt < MT; mt++)
#pragma unroll
            for (int nt = 0; nt < 8; nt++)
#pragma unroll
                for (int q = 0; q < 4; q++) acc[mt][nt][q] *= 0.125f;
        float mx[MT][2];
#pragma unroll
        for (int mt = 0; mt < MT; mt++)
#pragma unroll
            for (int h = 0; h < 2; h++) {
                float m = -3.4e38f;
#pragma unroll
                for (int nt = 0; nt < 8; nt++)
                    m = fmaxf(m, fmaxf(acc[mt][nt][2 * h], acc[mt][nt][2 * h + 1]));
                mx[mt][h] = m;
            }
#pragma unroll
        for (int off = 1; off <= 2; off <<= 1)
#pragma unroll
            for (int mt = 0; mt < MT; mt++)
#pragma unroll
                for (int h = 0; h < 2; h++)
                    mx[mt][h] = fmaxf(mx[mt][h], __shfl_xor_sync(0xffffffffu, mx[mt][h], off));
        if (lc == 0) {
#pragma unroll
            for (int mt = 0; mt < MT; mt++)
#pragma unroll
                for (int h = 0; h < 2; h++)
                    red[nw * BM + rbase + mt * 16 + h * 8] = mx[mt][h];
        }
        __syncthreads();
        float mf[MT][2];
#pragma unroll
        for (int mt = 0; mt < MT; mt++)
#pragma unroll
            for (int h = 0; h < 2; h++) {
                int rr = rbase + mt * 16 + h * 8;
                mf[mt][h] = fmaxf(fmaxf(red[rr], red[BM + rr]),
                                  fmaxf(red[2 * BM + rr], red[3 * BM + rr]));
            }
        __syncthreads();
        float sm2[MT][2];
#pragma unroll
        for (int mt = 0; mt < MT; mt++) { sm2[mt][0] = 0.f; sm2[mt][1] = 0.f; }
#pragma unroll
        for (int mt = 0; mt < MT; mt++)
#pragma unroll
            for (int nt = 0; nt < 8; nt++) {
                acc[mt][nt][0] = expf(acc[mt][nt][0] - mf[mt][0]);
                acc[mt][nt][1] = expf(acc[mt][nt][1] - mf[mt][0]);
                acc[mt][nt][2] = expf(acc[mt][nt][2] - mf[mt][1]);
                acc[mt][nt][3] = expf(acc[mt][nt][3] - mf[mt][1]);
                sm2[mt][0] += acc[mt][nt][0] + acc[mt][nt][1];
                sm2[mt][1] += acc[mt][nt][2] + acc[mt][nt][3];
            }
#pragma unroll
        for (int off = 1; off <= 2; off <<= 1)
#pragma unroll
            for (int mt = 0; mt < MT; mt++)
#pragma unroll
                for (int h = 0; h < 2; h++)
                    sm2[mt][h] += __shfl_xor_sync(0xffffffffu, sm2[mt][h], off);
        if (lc == 0) {
#pragma unroll
            for (int mt = 0; mt < MT; mt++)
#pragma unroll
                for (int h = 0; h < 2; h++)
                    red[nw * BM + rbase + mt * 16 + h * 8] = sm2[mt][h];
        }
        __syncthreads();
        float ri[MT][2];
#pragma unroll
        for (int mt = 0; mt < MT; mt++)
#pragma unroll
            for (int h = 0; h < 2; h++) {
                int rr = rbase + mt * 16 + h * 8;
                ri[mt][h] = 1.0f / (red[rr] + red[BM + rr] + red[2 * BM + rr] + red[3 * BM + rr]);
            }
#pragma unroll
        for (int mt = 0; mt < MT; mt++)
#pragma unroll
            for (int nt = 0; nt < 8; nt++) {
                int r = m0 + wmB + mt * 16 + lr;
                int c = n0 + wnB + nt * 8 + lc * 2;
                float v0 = tf32r(acc[mt][nt][0] * ri[mt][0]);
                float v1 = tf32r(acc[mt][nt][1] * ri[mt][0]);
                float v2 = tf32r(acc[mt][nt][2] * ri[mt][1]);
                float v3 = tf32r(acc[mt][nt][3] * ri[mt][1]);
                *reinterpret_cast<float2*>(C + (size_t)r * ldc + c)       = make_float2(v0, v1);
                *reinterpret_cast<float2*>(C + (size_t)(r + 8) * ldc + c) = make_float2(v2, v3);
            }
        return;
    }

    // ---- normal epilogue ----
#pragma unroll
    for (int mt = 0; mt < MT; mt++) {
#pragma unroll
        for (int nt = 0; nt < 8; nt++) {
            int r = m0 + wmB + mt * 16 + lr;
            int c = n0 + wnB + nt * 8 + lc * 2;
            float v0 = acc[mt][nt][0], v1 = acc[mt][nt][1];
            float v2 = acc[mt][nt][2], v3 = acc[mt][nt][3];
            if constexpr (EPI >= 1) {
                float bc0 = bias[c], bc1 = bias[c + 1];
                v0 += bc0; v1 += bc1; v2 += bc0; v3 += bc1;
            }
            if constexpr (EPI == 2) {
                v0 = gelu_exact(v0); v1 = gelu_exact(v1);
                v2 = gelu_exact(v2); v3 = gelu_exact(v3);
            }
            if constexpr (RO) {
                v0 = tf32r(v0); v1 = tf32r(v1); v2 = tf32r(v2); v3 = tf32r(v3);
            }
            *reinterpret_cast<float2*>(C + (size_t)r * ldc + c)       = make_float2(v0, v1);
            *reinterpret_cast<float2*>(C + (size_t)(r + 8) * ldc + c) = make_float2(v2, v3);
        }
    }
}

// ---------------- batched 32x32 tiled transpose (tf32-rounds output) --------
__global__ void transpose_r(const float* __restrict__ in, float* __restrict__ out,
                            int R, int C)
{
    __shared__ float t[32][33];
    long long zoff = (long long)blockIdx.z * R * C;
    int c0 = blockIdx.x * 32, r0 = blockIdx.y * 32;
    int x = threadIdx.x, y = threadIdx.y;
#pragma unroll
    for (int i = 0; i < 32; i += 8)
        t[y + i][x] = in[zoff + (long long)(r0 + y + i) * C + (c0 + x)];
    __syncthreads();
#pragma unroll
    for (int i = 0; i < 32; i += 8)
        out[zoff + (long long)(c0 + y + i) * R + (r0 + x)] = tf32r(t[x][y + i]);
}

// ---------------- elementwise tf32-round copy ----------------
__global__ void round_copy4(const float4* __restrict__ in, float4* __restrict__ out, int n4)
{
    int i = blockIdx.x * blockDim.x + threadIdx.x;
    if (i < n4) {
        float4 v = in[i];
        v.x = tf32r(v.x); v.y = tf32r(v.y); v.z = tf32r(v.z); v.w = tf32r(v.w);
        out[i] = v;
    }
}

// ---------------- split-K reduce (deterministic; rounds output) -------------
__global__ void reduce_slices(const float* __restrict__ part, float* __restrict__ out,
                              int n, int slices, long long stride)
{
    int i = blockIdx.x * blockDim.x + threadIdx.x;
    if (i < n) {
        float s = 0.f;
        for (int t = 0; t < slices; t++) s += part[i + (long long)t * stride];
        out[i] = tf32r(s);
    }
}

// ---------------- residual add + LayerNorm over D=1024 ----------------
__device__ __forceinline__ float block_sum_256(float v, float* sh)
{
#pragma unroll
    for (int o = 16; o; o >>= 1) v += __shfl_xor_sync(0xffffffffu, v, o);
    int w = threadIdx.x >> 5, lane = threadIdx.x & 31;
    if (lane == 0) sh[w] = v;
    __syncthreads();
    if (w == 0) {
        float t = (lane < 8) ? sh[lane] : 0.f;
#pragma unroll
        for (int o = 4; o; o >>= 1) t += __shfl_xor_sync(0xffffffffu, t, o);
        if (lane == 0) sh[0] = t;
    }
    __syncthreads();
    float r = sh[0];
    __syncthreads();
    return r;
}

__global__ void add_ln(const float* __restrict__ xa, const float* __restrict__ xb,
                       const float* __restrict__ g, const float* __restrict__ bt,
                       float* __restrict__ out)
{
    __shared__ float sh[8];
    int row = blockIdx.x;
    int tid = threadIdx.x;
    size_t base = (size_t)row * D_;
    float4 v = reinterpret_cast<const float4*>(xa + base)[tid];
    float4 r = reinterpret_cast<const float4*>(xb + base)[tid];
    v.x += r.x; v.y += r.y; v.z += r.z; v.w += r.w;
    float s = v.x + v.y + v.z + v.w;
    float mean = block_sum_256(s, sh) * (1.0f / D_);
    float d0 = v.x - mean, d1 = v.y - mean, d2 = v.z - mean, d3 = v.w - mean;
    float sq = d0 * d0 + d1 * d1 + d2 * d2 + d3 * d3;
    float var = block_sum_256(sq, sh) * (1.0f / D_);
    float rs = rsqrtf(var + 1e-12f);
    float4 gg = reinterpret_cast<const float4*>(g)[tid];
    float4 bb = reinterpret_cast<const float4*>(bt)[tid];
    float4 o;
    o.x = d0 * rs * gg.x + bb.x;
    o.y = d1 * rs * gg.y + bb.y;
    o.z = d2 * rs * gg.z + bb.z;
    o.w = d3 * rs * gg.w + bb.w;
    reinterpret_cast<float4*>(out + base)[tid] = o;
}

// ---------------- orchestration ----------------
extern "C" void kernel_launch(void* const* d_in, const int* in_sizes, int n_in,
                              void* d_out, int out_size)
{
    (void)in_sizes; (void)n_in; (void)out_size;
    const float* x   = (const float*)d_in[0];
    const float* Wq  = (const float*)d_in[1];
    const float* Wk  = (const float*)d_in[2];
    const float* Wv  = (const float*)d_in[3];
    const float* E   = (const float*)d_in[4];
    const float* F   = (const float*)d_in[5];
    const float* g1  = (const float*)d_in[6];
    const float* bl1 = (const float*)d_in[7];
    const float* W1  = (const float*)d_in[8];
    const float* bb1 = (const float*)d_in[9];
    const float* W2  = (const float*)d_in[10];
    const float* bb2 = (const float*)d_in[11];
    const float* g2  = (const float*)d_in[12];
    const float* bl2 = (const float*)d_in[13];
    float* out = (float*)d_out;

    float* S = nullptr;
    cudaGetSymbolAddress((void**)&S, g_scratch);
    float* qb  = S + OFF_Q;
    float* kbt = S + OFF_K;
    float* vbt = S + OFF_V;
    float* kp  = S + OFF_KP;
    float* vpt = S + OFF_VP;
    float* sc  = S + OFF_SC;
    float* t1  = S + OFF_T1;
    float* yb  = S + OFF_Y;
    float* hb  = S + OFF_HB;
    float* xb  = S + OFF_XB;
    float* kpp = S + OFF_KPP;
    float* wt  = S + OFF_WT;
    float* et  = S + OFF_ET;
    float* w1r = S + OFF_W1R;
    float* w2r = S + OFF_W2R;

    const long long NDll  = (long long)N_ * D_;
    const long long KPDll = (long long)KP_ * D_;
    const long long NKPll = (long long)N_ * KP_;
    const long long LLDD  = (long long)LL_ * D_ * D_;
    const size_t DD = (size_t)D_ * D_;

    const int SM128 = 2 * ((128 + 128) * 32 * 4);   // 65536
    const int SMSC  = 2 * ((64 + 256) * 32 * 4);    // 81920
    const int SM64  = 2 * ((128 + 64) * 32 * 4);    // 49152
    cudaFuncSetAttribute((const void*)gemm_ls<128, 128, 64, 0, true,  false, true,  false>, cudaFuncAttributeMaxDynamicSharedMemorySize, SM128);
    cudaFuncSetAttribute((const void*)gemm_ls<128, 128, 64, 0, false, true,  true,  false>, cudaFuncAttributeMaxDynamicSharedMemorySize, SM128);
    cudaFuncSetAttribute((const void*)gemm_ls<128, 128, 64, 0, false, false, false, false>, cudaFuncAttributeMaxDynamicSharedMemorySize, SM128);
    cudaFuncSetAttribute((const void*)gemm_ls<64,  256, 64, 0, false, false, false, true >, cudaFuncAttributeMaxDynamicSharedMemorySize, SMSC);
    cudaFuncSetAttribute((const void*)gemm_ls<128, 64,  32, 0, false, false, false, false>, cudaFuncAttributeMaxDynamicSharedMemorySize, SM64);
    cudaFuncSetAttribute((const void*)gemm_ls<128, 128, 64, 2, true,  false, true,  false>, cudaFuncAttributeMaxDynamicSharedMemorySize, SM128);
    cudaFuncSetAttribute((const void*)gemm_ls<128, 128, 64, 1, false, false, false, false>, cudaFuncAttributeMaxDynamicSharedMemorySize, SM128);

    dim3 tb(32, 8);

    // ---- once-per-launch pre-transforms (deterministic, idempotent) ----
    transpose_r<<<dim3(D_ / 32, D_ / 32, LL_), tb>>>(Wq, wt + 0 * LL_ * DD, D_, D_);
    transpose_r<<<dim3(D_ / 32, D_ / 32, LL_), tb>>>(Wk, wt + 1 * LL_ * DD, D_, D_);
    transpose_r<<<dim3(D_ / 32, D_ / 32, LL_), tb>>>(Wv, wt + 2 * LL_ * DD, D_, D_);
    transpose_r<<<dim3(KP_ / 32, N_ / 32, LL_), tb>>>(E, et, N_, KP_);
    transpose_r<<<dim3(KP_ / 32, N_ / 32, LL_), tb>>>(F, et + (size_t)LL_ * KP_ * N_, N_, KP_);
    {
        int n4 = LL_ * FF_ * D_ / 4;
        round_copy4<<<(n4 + 255) / 256, 256>>>((const float4*)W1, (float4*)w1r, n4);
        round_copy4<<<(n4 + 255) / 256, 256>>>((const float4*)W2, (float4*)w2r, n4);
    }

    for (int l = 0; l < LL_; l++) {
        const float* xin = (l == 0) ? x : xb;

        // --- q = x WqT : [8192,1024], A=x raw, B=wqT pre-rounded ---
        dim3 gQ(D_ / 128, (B_ * N_) / 128, 1);
        gemm_ls<128, 128, 64, 0, true, false, true, false><<<gQ, 128, SM128>>>(
            xin, wt + 0 * LL_ * DD + l * DD, qb, nullptr,
            D_, D_, D_, 0, 0, 0, 0, 0, 0, 0, 1, 1, D_);

        // --- kbt/vbt direct: C[d][token] = W^T x^T. zo: {Wk,Wv}, zi: batch ---
        dim3 gKV(N_ / 128, D_ / 128, 2 * B_);
        gemm_ls<128, 128, 64, 0, false, true, true, false><<<gKV, 128, SM128>>>(
            wt + 1 * LL_ * DD + l * DD, xin, kbt, nullptr,
            D_, D_, N_,
            0, LLDD, NDll, 0, NDll, (long long)BND_, 0, B_, 1, D_);

        // --- kpp: kp=E^T k -> [e][d];  vpp: vpt = v^T F -> [d][e]. split-K=8 ---
        dim3 gP1(D_ / 128, KP_ / 128, B_ * SPLITK_);
        gemm_ls<128, 128, 64, 0, false, false, false, false><<<gP1, 128, SM128>>>(
            et + (size_t)l * KP_ * N_, kbt, kpp, nullptr,
            N_, N_, D_,
            0, 0, NDll, 0, KPDll, 0, (long long)KPD_, B_, SPLITK_, N_);
        dim3 gP2(KP_ / 128, D_ / 128, B_ * SPLITK_);
        gemm_ls<128, 128, 64, 0, false, false, false, false><<<gP2, 128, SM128>>>(
            vbt, et + (size_t)(LL_ + l) * KP_ * N_, kpp + (size_t)SPLITK_ * KPD_, nullptr,
            N_, N_, KP_,
            NDll, 0, 0, 0, KPDll, 0, (long long)KPD_, B_, SPLITK_, N_);
        reduce_slices<<<KPD_ / 256, 256>>>(kpp, kp, KPD_, SPLITK_, (long long)KPD_);
        reduce_slices<<<KPD_ / 256, 256>>>(kpp + (size_t)SPLITK_ * KPD_, vpt, KPD_, SPLITK_, (long long)KPD_);

        // --- scores + fused softmax: BM=64, BN=256 (full rows), batched b*h ---
        dim3 gS(1, N_ / 64, B_ * H_);
        gemm_ls<64, 256, 64, 0, false, false, false, true><<<gS, 128, SMSC>>>(
            qb, kp, sc, nullptr,
            D_, D_, KP_,
            HD_, NDll, HD_, KPDll, NKPll, (long long)H_ * NKPll, 0, H_, 1, HD_);

        // --- attn = P VpT_h : A=sc [4096][256], B=vpt head rows [64][256] ---
        dim3 gA(1, N_ / 128, B_ * H_);
        gemm_ls<128, 64, 32, 0, false, false, false, false><<<gA, 128, SM64>>>(
            sc, vpt, t1, nullptr,
            KP_, KP_, D_,
            NKPll, (long long)H_ * NKPll, (long long)HD_ * KP_, (long long)D_ * KP_,
            HD_, NDll, 0, H_, 1, KP_);

        // --- y = LN(attn + x) ---
        add_ln<<<B_ * N_, 256>>>(t1, xin, g1 + (size_t)l * D_, bl1 + (size_t)l * D_, yb);

        // --- h = gelu(y W1^T + b1), output rounded ---
        dim3 gF1(FF_ / 128, (B_ * N_) / 128, 1);
        gemm_ls<128, 128, 64, 2, true, false, true, false><<<gF1, 128, SM128>>>(
            yb, w1r + (size_t)l * FF_ * D_, hb, bb1 + (size_t)l * FF_,
            D_, D_, FF_, 0, 0, 0, 0, 0, 0, 0, 1, 1, D_);

        // --- o = h W2^T + b2 ---
        dim3 gF2(D_ / 128, (B_ * N_) / 128, 1);
        gemm_ls<128, 128, 64, 1, false, false, false, false><<<gF2, 128, SM128>>>(
            hb, w2r + (size_t)l * D_ * FF_, t1, bb2 + (size_t)l * D_,
            FF_, FF_, D_, 0, 0, 0, 0, 0, 0, 0, 1, 1, FF_);

        // --- x_next = LN(o + y) ---
        add_ln<<<B_ * N_, 256>>>(t1, yb, g2 + (size_t)l * D_, bl2 + (size_t)l * D_,
                                 (l == LL_ - 1) ? out : xb);
    }
}

// round 10
// speedup vs baseline: 4.4610x; 1.5676x over previous
#include <cuda_runtime.h>
#include <cuda_fp16.h>
#include <math.h>
#include <stdint.h>

// ---------------- problem constants ----------------
#define LL_ 4
#define B_  2
#define N_  4096
#define D_  1024
#define H_  16
#define HD_ 64
#define KP_ 256
#define FF_ 4096

#define BND_  (B_*N_*D_)
#define KPD_  (B_*KP_*D_)
#define SCO_  (B_*H_*N_*KP_)
#define HBF_  (B_*N_*FF_)
#define SPLITK_ 8

// scratch layout (float units; half tensors use half the floats)
#define OFF_XH   ((size_t)0)
#define OFF_QH   (OFF_XH  + BND_/2)
#define OFF_KH   (OFF_QH  + BND_/2)
#define OFF_VH   (OFF_KH  + BND_/2)
#define OFF_KPH  (OFF_VH  + BND_/2)
#define OFF_VPH  (OFF_KPH + KPD_/2)
#define OFF_SCH  (OFF_VPH + KPD_/2)
#define OFF_T1   (OFF_SCH + SCO_/2)
#define OFF_YB   (OFF_T1  + BND_)
#define OFF_YBH  (OFF_YB  + BND_)
#define OFF_HBH  (OFF_YBH + BND_/2)
#define OFF_XB   (OFF_HBH + HBF_/2)
#define OFF_XBH  (OFF_XB  + BND_)
#define OFF_KPP  (OFF_XBH + BND_/2)
#define OFF_WTH  (OFF_KPP + (size_t)2*SPLITK_*KPD_)
#define OFF_ETH  (OFF_WTH + (size_t)3*LL_*D_*D_/2)
#define OFF_W1H  (OFF_ETH + (size_t)LL_*KP_*N_)
#define OFF_W2H  (OFF_W1H + (size_t)LL_*FF_*D_/2)
#define SCRATCH_FLOATS (OFF_W2H + (size_t)LL_*FF_*D_/2)

__device__ float g_scratch[SCRATCH_FLOATS];

// ---------------- helpers ----------------
__device__ __forceinline__ float gelu_exact(float x) {
    return 0.5f * x * (1.0f + erff(x * 0.70710678118654752f));
}
__device__ __forceinline__ uint32_t smem_u32(const void* p) {
    uint32_t a;
    asm("{ .reg .u64 t; cvta.to.shared.u64 t, %1; cvt.u32.u64 %0, t; }" : "=r"(a) : "l"(p));
    return a;
}
__device__ __forceinline__ void ldsm4(uint32_t r[4], uint32_t a) {
    asm volatile("ldmatrix.sync.aligned.m8n8.x4.shared.b16 {%0,%1,%2,%3}, [%4];"
                 : "=r"(r[0]), "=r"(r[1]), "=r"(r[2]), "=r"(r[3]) : "r"(a));
}
__device__ __forceinline__ void mma16(float c[4], const uint32_t a[4], uint32_t b0, uint32_t b1) {
    asm volatile(
        "mma.sync.aligned.m16n8k16.row.col.f32.f16.f16.f32 "
        "{%0,%1,%2,%3}, {%4,%5,%6,%7}, {%8,%9}, {%0,%1,%2,%3};"
        : "+f"(c[0]), "+f"(c[1]), "+f"(c[2]), "+f"(c[3])
        : "r"(a[0]), "r"(a[1]), "r"(a[2]), "r"(a[3]), "r"(b0), "r"(b1));
}
#define CP16(dst, src) asm volatile("cp.async.cg.shared.global [%0], [%1], 16;" :: "r"(dst), "l"(src))
#define CP_COMMIT()    asm volatile("cp.async.commit_group;" ::: "memory")
#define CP_WAIT(N)     asm volatile("cp.async.wait_group %0;" :: "n"(N) : "memory")

// ---------------- fp16 mma.sync GEMM: swizzled smem + ldmatrix + cp.async ----
// C(M,N) = A(M,K)*B^T(N,K): A gmem half [m][k] (lda), B gmem half [n][k] (ldb).
// BK=64 halves = 128B rows, 16B-unit xor swizzle u^(row&7). fp32 accumulate.
// Warp tile WM x 64; warp grid (BM/WM) x (BN/64).
// EPI: 0 none, 1 +bias(f32), 2 +bias+gelu. OH: emit half output (else float).
// SOFTM: fused row softmax (BN==256 full rows), emits half.
template<int BM, int BN, int WM, int EPI, bool OH, bool SOFTM>
__global__ void __launch_bounds__((BM/WM)*(BN/64)*32, 2)
gemm_h(const __half* __restrict__ Ag, const __half* __restrict__ Bg,
       void* __restrict__ Cg_, const float* __restrict__ bias,
       int lda, int ldb, int ldc,
       long long sAi, long long sAo, long long sBi, long long sBo,
       long long sCi, long long sCo, long long sCk,
       int binner, int splitK, int Kd)
{
    constexpr int BK = 64;
    constexpr int WGM = BM / WM;
    constexpr int MT  = WM / 16;
    constexpr int THREADS = WGM * (BN / 64) * 32;
    constexpr int ABY = BM * 128;
    constexpr int BBY = BN * 128;
    constexpr int STG = ABY + BBY;

    extern __shared__ char sm[];
    const uint32_t smb = smem_u32(sm);
    const int tid = threadIdx.x, w = tid >> 5, lane = tid & 31;
    const int l7 = lane & 7;

    const int z  = blockIdx.z;
    const int zk = z % splitK;
    const int zb = z / splitK;
    const int zi = zb % binner;
    const int zo = zb / binner;
    const __half* A  = Ag + zi * sAi + zo * sAo;
    const __half* Bp = Bg + zi * sBi + zo * sBo;
    const long long coff = zi * sCi + zo * sCo + (long long)zk * sCk;

    const int m0 = blockIdx.y * BM;
    const int n0 = blockIdx.x * BN;
    const int kPer = Kd / splitK;
    const int kbeg = zk * kPer;
    const int ntiles = kPer / BK;

    const int wmB = (w % WGM) * WM;
    const int wnB = (w / WGM) * 64;
    const int lr = lane >> 2, lc = lane & 3;

    float acc[MT][8][4];
#pragma unroll
    for (int i = 0; i < MT; i++)
#pragma unroll
        for (int j = 0; j < 8; j++)
#pragma unroll
            for (int q = 0; q < 4; q++) acc[i][j][q] = 0.f;

    auto stage = [&](int s, int kb) {
        uint32_t sa = smb + (uint32_t)(s * STG);
        uint32_t sb2 = sa + ABY;
#pragma unroll
        for (int t = 0; t < (BM * 8) / THREADS; t++) {
            int i = tid + t * THREADS;
            int m = i >> 3, u = i & 7;
            uint32_t dst = sa + (uint32_t)(m * 128 + ((u ^ (m & 7)) << 4));
            CP16(dst, (const void*)(A + (size_t)(m0 + m) * lda + kb + u * 8));
        }
#pragma unroll
        for (int t = 0; t < (BN * 8) / THREADS; t++) {
            int i = tid + t * THREADS;
            int n = i >> 3, u = i & 7;
            uint32_t dst = sb2 + (uint32_t)(n * 128 + ((u ^ (n & 7)) << 4));
            CP16(dst, (const void*)(Bp + (size_t)(n0 + n) * ldb + kb + u * 8));
        }
        CP_COMMIT();
    };

    auto compute = [&](int s) {
        uint32_t sa = smb + (uint32_t)(s * STG);
        uint32_t sb2 = sa + ABY;
        const int rrow = ((lane >> 3) & 1) * 8 + l7;   // ldmatrix row within 16
        const int ub   = lane >> 4;                    // k-half (16B unit) select
        uint32_t arow[MT], brow[4];
#pragma unroll
        for (int mt = 0; mt < MT; mt++)
            arow[mt] = sa + (uint32_t)((wmB + mt * 16 + rrow) * 128);
#pragma unroll
        for (int p = 0; p < 4; p++)
            brow[p] = sb2 + (uint32_t)((wnB + p * 16 + rrow) * 128);
#pragma unroll
        for (int ks = 0; ks < 4; ks++) {
            const uint32_t off = (uint32_t)((((ks * 2 + ub) ^ l7)) << 4);
            uint32_t a[MT][4], b[4][4];
#pragma unroll
            for (int mt = 0; mt < MT; mt++) ldsm4(a[mt], arow[mt] + off);
#pragma unroll
            for (int p = 0; p < 4; p++) ldsm4(b[p], brow[p] + off);
#pragma unroll
            for (int mt = 0; mt < MT; mt++)
#pragma unroll
                for (int p = 0; p < 4; p++) {
                    mma16(acc[mt][2 * p],     a[mt], b[p][0], b[p][2]);
                    mma16(acc[mt][2 * p + 1], a[mt], b[p][1], b[p][3]);
                }
        }
    };

    stage(0, kbeg);
    for (int t = 0; t < ntiles; t++) {
        int s = t & 1;
        if (t + 1 < ntiles) {
            stage(s ^ 1, kbeg + (t + 1) * BK);
            CP_WAIT(1);
        } else {
            CP_WAIT(0);
        }
        __syncthreads();
        compute(s);
        __syncthreads();
    }

    if constexpr (SOFTM) {
        // fused softmax over full BN(=256)-wide rows; scale 1/8 folded; half out.
        float* red = reinterpret_cast<float*>(sm);
        __half* Ch = (__half*)Cg_ + coff;
        const int nw = w / WGM;
        const int rbase = wmB + lr;
#pragma unroll
        for (int mt = 0; mt < MT; mt++)
#pragma unroll
            for (int nt = 0; nt < 8; nt++)
#pragma unroll
                for (int q = 0; q < 4; q++) acc[mt][nt][q] *= 0.125f;
        float mx[MT][2];
#pragma unroll
        for (int mt = 0; mt < MT; mt++)
#pragma unroll
            for (int h = 0; h < 2; h++) {
                float m = -3.4e38f;
#pragma unroll
                for (int nt = 0; nt < 8; nt++)
                    m = fmaxf(m, fmaxf(acc[mt][nt][2 * h], acc[mt][nt][2 * h + 1]));
                mx[mt][h] = m;
            }
#pragma unroll
        for (int off = 1; off <= 2; off <<= 1)
#pragma unroll
            for (int mt = 0; mt < MT; mt++)
#pragma unroll
                for (int h = 0; h < 2; h++)
                    mx[mt][h] = fmaxf(mx[mt][h], __shfl_xor_sync(0xffffffffu, mx[mt][h], off));
        if (lc == 0) {
#pragma unroll
            for (int mt = 0; mt < MT; mt++)
#pragma unroll
                for (int h = 0; h < 2; h++)
                    red[nw * BM + rbase + mt * 16 + h * 8] = mx[mt][h];
        }
        __syncthreads();
        float mf[MT][2];
#pragma unroll
        for (int mt = 0; mt < MT; mt++)
#pragma unroll
            for (int h = 0; h < 2; h++) {
                int rr = rbase + mt * 16 + h * 8;
                mf[mt][h] = fmaxf(fmaxf(red[rr], red[BM + rr]),
                                  fmaxf(red[2 * BM + rr], red[3 * BM + rr]));
            }
        __syncthreads();
        float sm2[MT][2];
#pragma unroll
        for (int mt = 0; mt < MT; mt++) { sm2[mt][0] = 0.f; sm2[mt][1] = 0.f; }
#pragma unroll
        for (int mt = 0; mt < MT; mt++)
#pragma unroll
            for (int nt = 0; nt < 8; nt++) {
                acc[mt][nt][0] = expf(acc[mt][nt][0] - mf[mt][0]);
                acc[mt][nt][1] = expf(acc[mt][nt][1] - mf[mt][0]);
                acc[mt][nt][2] = expf(acc[mt][nt][2] - mf[mt][1]);
                acc[mt][nt][3] = expf(acc[mt][nt][3] - mf[mt][1]);
                sm2[mt][0] += acc[mt][nt][0] + acc[mt][nt][1];
                sm2[mt][1] += acc[mt][nt][2] + acc[mt][nt][3];
            }
#pragma unroll
        for (int off = 1; off <= 2; off <<= 1)
#pragma unroll
            for (int mt = 0; mt < MT; mt++)
#pragma unroll
                for (int h = 0; h < 2; h++)
                    sm2[mt][h] += __shfl_xor_sync(0xffffffffu, sm2[mt][h], off);
        if (lc == 0) {
#pragma unroll
            for (int mt = 0; mt < MT; mt++)
#pragma unroll
                for (int h = 0; h < 2; h++)
                    red[nw * BM + rbase + mt * 16 + h * 8] = sm2[mt][h];
        }
        __syncthreads();
        float ri[MT][2];
#pragma unroll
        for (int mt = 0; mt < MT; mt++)
#pragma unroll
            for (int h = 0; h < 2; h++) {
                int rr = rbase + mt * 16 + h * 8;
                ri[mt][h] = 1.0f / (red[rr] + red[BM + rr] + red[2 * BM + rr] + red[3 * BM + rr]);
            }
#pragma unroll
        for (int mt = 0; mt < MT; mt++)
#pragma unroll
            for (int nt = 0; nt < 8; nt++) {
                int r = m0 + wmB + mt * 16 + lr;
                int c = n0 + wnB + nt * 8 + lc * 2;
                *reinterpret_cast<__half2*>(Ch + (size_t)r * ldc + c) =
                    __floats2half2_rn(acc[mt][nt][0] * ri[mt][0], acc[mt][nt][1] * ri[mt][0]);
                *reinterpret_cast<__half2*>(Ch + (size_t)(r + 8) * ldc + c) =
                    __floats2half2_rn(acc[mt][nt][2] * ri[mt][1], acc[mt][nt][3] * ri[mt][1]);
            }
        return;
    }

    // ---- normal epilogue ----
#pragma unroll
    for (int mt = 0; mt < MT; mt++) {
#pragma unroll
        for (int nt = 0; nt < 8; nt++) {
            int r = m0 + wmB + mt * 16 + lr;
            int c = n0 + wnB + nt * 8 + lc * 2;
            float v0 = acc[mt][nt][0], v1 = acc[mt][nt][1];
            float v2 = acc[mt][nt][2], v3 = acc[mt][nt][3];
            if constexpr (EPI >= 1) {
                float bc0 = bias[c], bc1 = bias[c + 1];
                v0 += bc0; v1 += bc1; v2 += bc0; v3 += bc1;
            }
            if constexpr (EPI == 2) {
                v0 = gelu_exact(v0); v1 = gelu_exact(v1);
                v2 = gelu_exact(v2); v3 = gelu_exact(v3);
            }
            if constexpr (OH) {
                __half* Ch = (__half*)Cg_ + coff;
                *reinterpret_cast<__half2*>(Ch + (size_t)r * ldc + c)       = __floats2half2_rn(v0, v1);
                *reinterpret_cast<__half2*>(Ch + (size_t)(r + 8) * ldc + c) = __floats2half2_rn(v2, v3);
            } else {
                float* Cf = (float*)Cg_ + coff;
                *reinterpret_cast<float2*>(Cf + (size_t)r * ldc + c)       = make_float2(v0, v1);
                *reinterpret_cast<float2*>(Cf + (size_t)(r + 8) * ldc + c) = make_float2(v2, v3);
            }
        }
    }
}

// ---------------- batched 32x32 tiled transpose, fp32 -> half --------------
__global__ void transpose_h(const float* __restrict__ in, __half* __restrict__ out,
                            int R, int C)
{
    __shared__ float t[32][33];
    long long zoff = (long long)blockIdx.z * R * C;
    int c0 = blockIdx.x * 32, r0 = blockIdx.y * 32;
    int x = threadIdx.x, y = threadIdx.y;
#pragma unroll
    for (int i = 0; i < 32; i += 8)
        t[y + i][x] = in[zoff + (long long)(r0 + y + i) * C + (c0 + x)];
    __syncthreads();
#pragma unroll
    for (int i = 0; i < 32; i += 8)
        out[zoff + (long long)(c0 + y + i) * R + (r0 + x)] = __float2half(t[x][y + i]);
}

// ---------------- elementwise fp32 -> half convert ----------------
__global__ void conv_h(const float4* __restrict__ in, __half2* __restrict__ out, int n4)
{
    int i = blockIdx.x * blockDim.x + threadIdx.x;
    if (i < n4) {
        float4 v = in[i];
        out[2 * i]     = __floats2half2_rn(v.x, v.y);
        out[2 * i + 1] = __floats2half2_rn(v.z, v.w);
    }
}

// ---------------- split-K reduce (deterministic; half out) -------------
__global__ void reduce_h(const float* __restrict__ part, __half* __restrict__ out,
                         int n, int slices, long long stride)
{
    int i = blockIdx.x * blockDim.x + threadIdx.x;
    if (i < n) {
        float s = 0.f;
        for (int t = 0; t < slices; t++) s += part[i + (long long)t * stride];
        out[i] = __float2half(s);
    }
}

// ---------------- residual add + LayerNorm over D=1024 ----------------
__device__ __forceinline__ float block_sum_256(float v, float* sh)
{
#pragma unroll
    for (int o = 16; o; o >>= 1) v += __shfl_xor_sync(0xffffffffu, v, o);
    int w = threadIdx.x >> 5, lane = threadIdx.x & 31;
    if (lane == 0) sh[w] = v;
    __syncthreads();
    if (w == 0) {
        float t = (lane < 8) ? sh[lane] : 0.f;
#pragma unroll
        for (int o = 4; o; o >>= 1) t += __shfl_xor_sync(0xffffffffu, t, o);
        if (lane == 0) sh[0] = t;
    }
    __syncthreads();
    float r = sh[0];
    __syncthreads();
    return r;
}

__global__ void add_ln(const float* __restrict__ xa, const float* __restrict__ xb,
                       const float* __restrict__ g, const float* __restrict__ bt,
                       float* __restrict__ out, __half* __restrict__ outh)
{
    __shared__ float sh[8];
    int row = blockIdx.x;
    int tid = threadIdx.x;
    size_t base = (size_t)row * D_;
    float4 v = reinterpret_cast<const float4*>(xa + base)[tid];
    float4 r = reinterpret_cast<const float4*>(xb + base)[tid];
    v.x += r.x; v.y += r.y; v.z += r.z; v.w += r.w;
    float s = v.x + v.y + v.z + v.w;
    float mean = block_sum_256(s, sh) * (1.0f / D_);
    float d0 = v.x - mean, d1 = v.y - mean, d2 = v.z - mean, d3 = v.w - mean;
    float sq = d0 * d0 + d1 * d1 + d2 * d2 + d3 * d3;
    float var = block_sum_256(sq, sh) * (1.0f / D_);
    float rs = rsqrtf(var + 1e-12f);
    float4 gg = reinterpret_cast<const float4*>(g)[tid];
    float4 bb = reinterpret_cast<const float4*>(bt)[tid];
    float4 o;
    o.x = d0 * rs * gg.x + bb.x;
    o.y = d1 * rs * gg.y + bb.y;
    o.z = d2 * rs * gg.z + bb.z;
    o.w = d3 * rs * gg.w + bb.w;
    reinterpret_cast<float4*>(out + base)[tid] = o;
    if (outh) {
        *reinterpret_cast<__half2*>(outh + base + tid * 4)     = __floats2half2_rn(o.x, o.y);
        *reinterpret_cast<__half2*>(outh + base + tid * 4 + 2) = __floats2half2_rn(o.z, o.w);
    }
}

// ---------------- orchestration ----------------
extern "C" void kernel_launch(void* const* d_in, const int* in_sizes, int n_in,
                              void* d_out, int out_size)
{
    (void)in_sizes; (void)n_in; (void)out_size;
    const float* x   = (const float*)d_in[0];
    const float* Wq  = (const float*)d_in[1];
    const float* Wk  = (const float*)d_in[2];
    const float* Wv  = (const float*)d_in[3];
    const float* E   = (const float*)d_in[4];
    const float* F   = (const float*)d_in[5];
    const float* g1  = (const float*)d_in[6];
    const float* bl1 = (const float*)d_in[7];
    const float* W1  = (const float*)d_in[8];
    const float* bb1 = (const float*)d_in[9];
    const float* W2  = (const float*)d_in[10];
    const float* bb2 = (const float*)d_in[11];
    const float* g2  = (const float*)d_in[12];
    const float* bl2 = (const float*)d_in[13];
    float* out = (float*)d_out;

    float* S = nullptr;
    cudaGetSymbolAddress((void**)&S, g_scratch);
    __half* x_h   = (__half*)(S + OFF_XH);
    __half* qb_h  = (__half*)(S + OFF_QH);
    __half* kbt_h = (__half*)(S + OFF_KH);
    __half* kp_h  = (__half*)(S + OFF_KPH);
    __half* vpt_h = (__half*)(S + OFF_VPH);
    __half* sc_h  = (__half*)(S + OFF_SCH);
    float*  t1    = S + OFF_T1;
    float*  yb    = S + OFF_YB;
    __half* yb_h  = (__half*)(S + OFF_YBH);
    __half* hb_h  = (__half*)(S + OFF_HBH);
    float*  xb    = S + OFF_XB;
    __half* xb_h  = (__half*)(S + OFF_XBH);
    float*  kpp   = S + OFF_KPP;
    __half* wt_h  = (__half*)(S + OFF_WTH);
    __half* et_h  = (__half*)(S + OFF_ETH);
    __half* w1_h  = (__half*)(S + OFF_W1H);
    __half* w2_h  = (__half*)(S + OFF_W2H);
    __half* vbt_h = kbt_h + (size_t)BND_;   // [b][d][t] for V, after K's 2 batches

    const long long NDll  = (long long)N_ * D_;
    const long long KPDll = (long long)KP_ * D_;
    const long long NKPll = (long long)N_ * KP_;
    const long long LLDD  = (long long)LL_ * D_ * D_;
    const long long BNDll = (long long)BND_;
    const size_t DD = (size_t)D_ * D_;

    const int SM128 = 2 * (128 + 128) * 128;  // 65536
    const int SMSC  = 2 * (64 + 256) * 128;   // 81920
    const int SM64  = 2 * (128 + 64) * 128;   // 49152
    cudaFuncSetAttribute((const void*)gemm_h<128, 128, 64, 0, true,  false>, cudaFuncAttributeMaxDynamicSharedMemorySize, SM128);
    cudaFuncSetAttribute((const void*)gemm_h<128, 128, 64, 0, false, false>, cudaFuncAttributeMaxDynamicSharedMemorySize, SM128);
    cudaFuncSetAttribute((const void*)gemm_h<64,  256, 64, 0, true,  true >, cudaFuncAttributeMaxDynamicSharedMemorySize, SMSC);
    cudaFuncSetAttribute((const void*)gemm_h<128, 64,  32, 0, false, false>, cudaFuncAttributeMaxDynamicSharedMemorySize, SM64);
    cudaFuncSetAttribute((const void*)gemm_h<128, 128, 64, 2, true,  false>, cudaFuncAttributeMaxDynamicSharedMemorySize, SM128);
    cudaFuncSetAttribute((const void*)gemm_h<128, 128, 64, 1, false, false>, cudaFuncAttributeMaxDynamicSharedMemorySize, SM128);

    dim3 tb(32, 8);

    // ---- once-per-launch pre-transforms (deterministic, idempotent) ----
    transpose_h<<<dim3(D_ / 32, D_ / 32, LL_), tb>>>(Wq, wt_h + 0 * LL_ * DD, D_, D_);
    transpose_h<<<dim3(D_ / 32, D_ / 32, LL_), tb>>>(Wk, wt_h + 1 * LL_ * DD, D_, D_);
    transpose_h<<<dim3(D_ / 32, D_ / 32, LL_), tb>>>(Wv, wt_h + 2 * LL_ * DD, D_, D_);
    transpose_h<<<dim3(KP_ / 32, N_ / 32, LL_), tb>>>(E, et_h, N_, KP_);
    transpose_h<<<dim3(KP_ / 32, N_ / 32, LL_), tb>>>(F, et_h + (size_t)LL_ * KP_ * N_, N_, KP_);
    {
        int n4 = LL_ * FF_ * D_ / 4;
        conv_h<<<(n4 + 255) / 256, 256>>>((const float4*)W1, (__half2*)w1_h, n4);
        conv_h<<<(n4 + 255) / 256, 256>>>((const float4*)W2, (__half2*)w2_h, n4);
        int nx = BND_ / 4;
        conv_h<<<(nx + 255) / 256, 256>>>((const float4*)x, (__half2*)x_h, nx);
    }

    for (int l = 0; l < LL_; l++) {
        const __half* xin_h = (l == 0) ? x_h : xb_h;
        const float*  xin_f = (l == 0) ? x : xb;

        // --- q = x WqT : half in/out ---
        dim3 gQ(D_ / 128, (B_ * N_) / 128, 1);
        gemm_h<128, 128, 64, 0, true, false><<<gQ, 128, SM128>>>(
            xin_h, wt_h + 0 * LL_ * DD + l * DD, qb_h, nullptr,
            D_, D_, D_, 0, 0, 0, 0, 0, 0, 0, 1, 1, D_);

        // --- kbt/vbt direct: C[d][token] = W^T x^T. zo: {Wk,Wv}, zi: batch ---
        dim3 gKV(N_ / 128, D_ / 128, 2 * B_);
        gemm_h<128, 128, 64, 0, true, false><<<gKV, 128, SM128>>>(
            wt_h + 1 * LL_ * DD + l * DD, xin_h, kbt_h, nullptr,
            D_, D_, N_,
            0, LLDD, NDll, 0, NDll, BNDll, 0, B_, 1, D_);

        // --- kp = E^T k -> [e][d]; vpt = v^T F -> [d][e]. split-K=8, f32 partials ---
        dim3 gP1(D_ / 128, KP_ / 128, B_ * SPLITK_);
        gemm_h<128, 128, 64, 0, false, false><<<gP1, 128, SM128>>>(
            et_h + (size_t)l * KP_ * N_, kbt_h, kpp, nullptr,
            N_, N_, D_,
            0, 0, NDll, 0, KPDll, 0, (long long)KPD_, B_, SPLITK_, N_);
        dim3 gP2(KP_ / 128, D_ / 128, B_ * SPLITK_);
        gemm_h<128, 128, 64, 0, false, false><<<gP2, 128, SM128>>>(
            vbt_h, et_h + (size_t)(LL_ + l) * KP_ * N_, kpp + (size_t)SPLITK_ * KPD_, nullptr,
            N_, N_, KP_,
            NDll, 0, 0, 0, KPDll, 0, (long long)KPD_, B_, SPLITK_, N_);
        reduce_h<<<KPD_ / 256, 256>>>(kpp, kp_h, KPD_, SPLITK_, (long long)KPD_);
        reduce_h<<<KPD_ / 256, 256>>>(kpp + (size_t)SPLITK_ * KPD_, vpt_h, KPD_, SPLITK_, (long long)KPD_);

        // --- scores + fused softmax: BM=64, BN=256 (full rows), batched b*h ---
        dim3 gS(1, N_ / 64, B_ * H_);
        gemm_h<64, 256, 64, 0, true, true><<<gS, 128, SMSC>>>(
            qb_h, kp_h, sc_h, nullptr,
            D_, D_, KP_,
            HD_, NDll, HD_, KPDll, NKPll, (long long)H_ * NKPll, 0, H_, 1, HD_);

        // --- attn = P VpT_h : A=sc_h [token][256], B=vpt head rows [64][256] ---
        dim3 gA(1, N_ / 128, B_ * H_);
        gemm_h<128, 64, 32, 0, false, false><<<gA, 128, SM64>>>(
            sc_h, vpt_h, t1, nullptr,
            KP_, KP_, D_,
            NKPll, (long long)H_ * NKPll, (long long)HD_ * KP_, (long long)D_ * KP_,
            HD_, NDll, 0, H_, 1, KP_);

        // --- y = LN(attn + x): fp32 residual + half GEMM operand ---
        add_ln<<<B_ * N_, 256>>>(t1, xin_f, g1 + (size_t)l * D_, bl1 + (size_t)l * D_, yb, yb_h);

        // --- h = gelu(y W1^T + b1): half out ---
        dim3 gF1(FF_ / 128, (B_ * N_) / 128, 1);
        gemm_h<128, 128, 64, 2, true, false><<<gF1, 128, SM128>>>(
            yb_h, w1_h + (size_t)l * FF_ * D_, hb_h, bb1 + (size_t)l * FF_,
            D_, D_, FF_, 0, 0, 0, 0, 0, 0, 0, 1, 1, D_);

        // --- o = h W2^T + b2: f32 out ---
        dim3 gF2(D_ / 128, (B_ * N_) / 128, 1);
        gemm_h<128, 128, 64, 1, false, false><<<gF2, 128, SM128>>>(
            hb_h, w2_h + (size_t)l * D_ * FF_, t1, bb2 + (size_t)l * D_,
            FF_, FF_, D_, 0, 0, 0, 0, 0, 0, 0, 1, 1, FF_);

        // --- x_next = LN(o + y) ---
        add_ln<<<B_ * N_, 256>>>(t1, yb, g2 + (size_t)l * D_, bl2 + (size_t)l * D_,
                                 (l == LL_ - 1) ? out : xb,
                                 (l == LL_ - 1) ? (__half*)nullptr : xb_h);
    }
}